// round 6
// baseline (speedup 1.0000x reference)
#include <cuda_runtime.h>

#define NODES 100000
#define EDGES 640000
#define DIM   128
#define NDIN  239
#define NEG   0.01f

// ---- scratch (__device__ globals; no allocs allowed) ----
__device__ float g_bufA[(size_t)NODES * DIM];
__device__ float g_bufB[(size_t)NODES * DIM];
__device__ float g_bufC[(size_t)NODES * DIM];
__device__ float g_deg[NODES];
__device__ float g_dinv[NODES];
__device__ float g_norm[EDGES];

// ---------------- graph-structure kernels ----------------
__global__ void k_zero_deg() {
    int i = blockIdx.x * blockDim.x + threadIdx.x;
    if (i < NODES) g_deg[i] = 0.f;
}

__global__ void k_deg(const int* __restrict__ ei) {
    int e = blockIdx.x * blockDim.x + threadIdx.x;
    if (e < EDGES) atomicAdd(&g_deg[ei[EDGES + e]], 1.f);
}

__global__ void k_dinv() {
    int i = blockIdx.x * blockDim.x + threadIdx.x;
    if (i < NODES) g_dinv[i] = rsqrtf(g_deg[i] + 1.f);
}

__global__ void k_norm(const int* __restrict__ ei) {
    int e = blockIdx.x * blockDim.x + threadIdx.x;
    if (e < EDGES) {
        int s = ei[e];
        int d = ei[EDGES + e];
        g_norm[e] = g_dinv[s] * g_dinv[d];
    }
}

// ---------------- f32x2 helpers ----------------
__device__ __forceinline__ unsigned long long pack_dup(float v) {
    unsigned long long p;
    asm("mov.b64 %0, {%1, %1};" : "=l"(p) : "f"(v));
    return p;
}
__device__ __forceinline__ unsigned long long pack2(float a, float b) {
    unsigned long long p;
    asm("mov.b64 %0, {%1, %2};" : "=l"(p) : "f"(a), "f"(b));
    return p;
}
__device__ __forceinline__ void unpack2(unsigned long long p, float& a, float& b) {
    asm("mov.b64 {%0, %1}, %2;" : "=f"(a), "=f"(b) : "l"(p));
}
#define FMA2(d, a, b) \
    asm("fma.rn.f32x2 %0, %1, %2, %0;" : "+l"(d) : "l"(a), "l"(b))

// ---------------- GEMM: out[M,128] = A[M,K] @ W[K,128] ----------------
// 128x128 block tile, 256 threads (16x16), 8x8 microtile (ADJACENT rows),
// packed f32x2 FMA. A stored pre-duplicated (a,a); W stored as packed pairs.
// LEAKY: out = leaky(acc + bias)
// CONV : out = acc (hw); agg = acc*dinv[row]^2 + bias  (self-loop fused)
template <bool LEAKY, bool CONV>
__global__ void __launch_bounds__(256)
k_gemm(const float* __restrict__ A, const float* __restrict__ W,
       const float* __restrict__ bias,
       float* __restrict__ out, float* __restrict__ agg,
       int M, int K) {
    __shared__ __align__(16) unsigned long long as_dup[16][130]; // (a,a) [k][row]
    __shared__ __align__(16) unsigned long long ws[16][64];      // w pairs [k][col/2]

    int tx = threadIdx.x;            // 0..15 -> cols 8*tx .. 8*tx+7
    int ty = threadIdx.y;            // 0..15 -> rows 8*ty .. 8*ty+7 (adjacent)
    int tid = ty * 16 + tx;
    int row0 = blockIdx.x * 128;

    unsigned long long acc[8][4];
#pragma unroll
    for (int i = 0; i < 8; i++)
#pragma unroll
        for (int j = 0; j < 4; j++) acc[i][j] = 0ull;

    int nch = (K + 15) >> 4;
    for (int ch = 0; ch < nch; ch++) {
        int k0 = ch << 4;
        // A tile: 128 rows x 16 k -> duplicated pairs, [k][row] layout
#pragma unroll
        for (int j = 0; j < 8; j++) {
            int idx = tid + 256 * j;
            int c = idx & 15, r = idx >> 4;
            int gr = row0 + r, gc = k0 + c;
            float v = (gr < M && gc < K) ? A[(long)gr * K + gc] : 0.f;
            as_dup[c][r] = pack_dup(v);
        }
        // W tile: 16 x 128 floats -> packed pairs
#pragma unroll
        for (int j = 0; j < 2; j++) {
            int idx = tid + 256 * j;       // float4 index 0..511
            int k = idx >> 5, c4 = idx & 31;
            float4 v = make_float4(0.f, 0.f, 0.f, 0.f);
            if (k0 + k < K) v = *(const float4*)&W[(long)(k0 + k) * 128 + c4 * 4];
            ws[k][c4 * 2]     = pack2(v.x, v.y);
            ws[k][c4 * 2 + 1] = pack2(v.z, v.w);
        }
        __syncthreads();
#pragma unroll
        for (int k = 0; k < 16; k++) {
            ulonglong2 w01 = *(ulonglong2*)&ws[k][tx * 4];
            ulonglong2 w23 = *(ulonglong2*)&ws[k][tx * 4 + 2];
            // 4x LDS.128: two duplicated-A pairs each (adjacent rows)
            ulonglong2 a01 = *(ulonglong2*)&as_dup[k][ty * 8];
            ulonglong2 a23 = *(ulonglong2*)&as_dup[k][ty * 8 + 2];
            ulonglong2 a45 = *(ulonglong2*)&as_dup[k][ty * 8 + 4];
            ulonglong2 a67 = *(ulonglong2*)&as_dup[k][ty * 8 + 6];
            unsigned long long ar[8] = {a01.x, a01.y, a23.x, a23.y,
                                        a45.x, a45.y, a67.x, a67.y};
#pragma unroll
            for (int i = 0; i < 8; i++) {
                FMA2(acc[i][0], ar[i], w01.x);
                FMA2(acc[i][1], ar[i], w01.y);
                FMA2(acc[i][2], ar[i], w23.x);
                FMA2(acc[i][3], ar[i], w23.y);
            }
        }
        __syncthreads();
    }

    int cb = tx * 8;
    float4 b0 = *(const float4*)&bias[cb];
    float4 b1 = *(const float4*)&bias[cb + 4];
#pragma unroll
    for (int i = 0; i < 8; i++) {
        int r = row0 + ty * 8 + i;
        if (r >= M) continue;
        float4 v0, v1;
        unpack2(acc[i][0], v0.x, v0.y);
        unpack2(acc[i][1], v0.z, v0.w);
        unpack2(acc[i][2], v1.x, v1.y);
        unpack2(acc[i][3], v1.z, v1.w);
        long base = (long)r * 128 + cb;
        if (CONV) {
            *(float4*)&out[base]     = v0;   // hw for edge scatter
            *(float4*)&out[base + 4] = v1;
            float di = g_dinv[r];
            float s = di * di;
            float4 a0 = make_float4(fmaf(v0.x, s, b0.x), fmaf(v0.y, s, b0.y),
                                    fmaf(v0.z, s, b0.z), fmaf(v0.w, s, b0.w));
            float4 a1 = make_float4(fmaf(v1.x, s, b1.x), fmaf(v1.y, s, b1.y),
                                    fmaf(v1.z, s, b1.z), fmaf(v1.w, s, b1.w));
            *(float4*)&agg[base]     = a0;
            *(float4*)&agg[base + 4] = a1;
        } else {
            v0.x += b0.x; v0.y += b0.y; v0.z += b0.z; v0.w += b0.w;
            v1.x += b1.x; v1.y += b1.y; v1.z += b1.z; v1.w += b1.w;
            if (LEAKY) {
                v0.x = fmaxf(v0.x, NEG * v0.x); v0.y = fmaxf(v0.y, NEG * v0.y);
                v0.z = fmaxf(v0.z, NEG * v0.z); v0.w = fmaxf(v0.w, NEG * v0.w);
                v1.x = fmaxf(v1.x, NEG * v1.x); v1.y = fmaxf(v1.y, NEG * v1.y);
                v1.z = fmaxf(v1.z, NEG * v1.z); v1.w = fmaxf(v1.w, NEG * v1.w);
            }
            *(float4*)&out[base]     = v0;
            *(float4*)&out[base + 4] = v1;
        }
    }
}

// ---------------- edge scatter: agg[dst] += hw[src] * norm ----------------
// One warp per edge; lane c handles one float4. red.global.add.v4.f32.
__global__ void k_scatter(const int* __restrict__ ei,
                          const float* __restrict__ hw,
                          float* __restrict__ agg) {
    int idx = blockIdx.x * blockDim.x + threadIdx.x;
    int e = idx >> 5;
    int c = idx & 31;
    if (e >= EDGES) return;
    int src = ei[e];
    int dst = ei[EDGES + e];
    float n = g_norm[e];
    float4 v = *(const float4*)&hw[(long)src * 128 + c * 4];
    float* p = &agg[(long)dst * 128 + c * 4];
    asm volatile("red.global.add.v4.f32 [%0], {%1, %2, %3, %4};"
                 :: "l"(p), "f"(v.x * n), "f"(v.y * n), "f"(v.z * n), "f"(v.w * n)
                 : "memory");
}

// ---------------- final projection: out[M,2] = h[M,128] @ W[128,2] + b ----------------
__global__ void k_out(const float* __restrict__ h, const float* __restrict__ W,
                      const float* __restrict__ b, float* __restrict__ out) {
    __shared__ float ws[256];
    int tid = threadIdx.x;
    if (tid < 256) ws[tid] = W[tid];
    __syncthreads();
    int warp = (blockIdx.x * blockDim.x + tid) >> 5;
    int lane = tid & 31;
    if (warp >= NODES) return;
    float4 v = *(const float4*)&h[(long)warp * 128 + lane * 4];
    int k = lane * 4;
    float s0 = v.x * ws[(k + 0) * 2] + v.y * ws[(k + 1) * 2] +
               v.z * ws[(k + 2) * 2] + v.w * ws[(k + 3) * 2];
    float s1 = v.x * ws[(k + 0) * 2 + 1] + v.y * ws[(k + 1) * 2 + 1] +
               v.z * ws[(k + 2) * 2 + 1] + v.w * ws[(k + 3) * 2 + 1];
#pragma unroll
    for (int o = 16; o; o >>= 1) {
        s0 += __shfl_xor_sync(0xFFFFFFFFu, s0, o);
        s1 += __shfl_xor_sync(0xFFFFFFFFu, s1, o);
    }
    if (lane == 0) {
        out[(long)warp * 2 + 0] = s0 + b[0];
        out[(long)warp * 2 + 1] = s1 + b[1];
    }
}

// ---------------- launch ----------------
extern "C" void kernel_launch(void* const* d_in, const int* in_sizes, int n_in,
                              void* d_out, int out_size) {
    int ix, iei, iwin, ibin, iwg, ibg, iwo1, ibo1, iwo2, ibo2;
    if (in_sizes[0] == 16384) {          // alphabetical (hedge)
        iwg = 0; iwin = 1; iwo1 = 2; iwo2 = 3;
        ibg = 4; ibin = 5; ibo1 = 6; ibo2 = 7;
        iei = 8; ix = 10;
    } else {                              // dict / insertion order
        ix = 0; iei = 1;
        iwin = 3; ibin = 4; iwg = 5; ibg = 6;
        iwo1 = 7; ibo1 = 8; iwo2 = 9; ibo2 = 10;
    }

    const float* x    = (const float*)d_in[ix];
    const int*   ei   = (const int*)d_in[iei];   // int32 (JAX x64 disabled)
    const float* W_in = (const float*)d_in[iwin];
    const float* b_in = (const float*)d_in[ibin];
    const float* W_g  = (const float*)d_in[iwg];
    const float* b_g  = (const float*)d_in[ibg];
    const float* W_o1 = (const float*)d_in[iwo1];
    const float* b_o1 = (const float*)d_in[ibo1];
    const float* W_o2 = (const float*)d_in[iwo2];
    const float* b_o2 = (const float*)d_in[ibo2];
    float* out = (float*)d_out;

    float *bufA, *bufB, *bufC;
    cudaGetSymbolAddress((void**)&bufA, g_bufA);
    cudaGetSymbolAddress((void**)&bufB, g_bufB);
    cudaGetSymbolAddress((void**)&bufC, g_bufC);

    dim3 gblk(16, 16);
    int gemm_grid = (NODES + 127) / 128;
    int scat_grid = (EDGES * 32 + 255) / 256;

    // Launch order: the big K=239 GEMM sits at index 3 (the one ncu captures).
    k_zero_deg<<<(NODES + 255) / 256, 256>>>();                          // 0
    k_deg<<<(EDGES + 255) / 256, 256>>>(ei);                             // 1
    k_dinv<<<(NODES + 255) / 256, 256>>>();                              // 2
    // h0 = leaky(x @ W_in + b_in) -> bufA                               // 3 (profiled)
    k_gemm<true, false><<<gemm_grid, gblk>>>(x, W_in, b_in, bufA, nullptr, NODES, NDIN);
    k_norm<<<(EDGES + 255) / 256, 256>>>(ei);                            // 4

    // conv1: hw -> bufB ; agg(self+bias) -> bufC ; scatter into bufC
    k_gemm<false, true><<<gemm_grid, gblk>>>(bufA, W_g, b_g, bufB, bufC, NODES, DIM);
    k_scatter<<<scat_grid, 256>>>(ei, bufB, bufC);

    // conv2: hw -> bufB ; agg -> bufA ; scatter into bufA
    k_gemm<false, true><<<gemm_grid, gblk>>>(bufC, W_g, b_g, bufB, bufA, NODES, DIM);
    k_scatter<<<scat_grid, 256>>>(ei, bufB, bufA);

    // h3 = leaky(bufA @ W_o1 + b_o1) -> bufC
    k_gemm<true, false><<<gemm_grid, gblk>>>(bufA, W_o1, b_o1, bufC, nullptr, NODES, DIM);

    // out = bufC @ W_o2 + b_o2
    k_out<<<(NODES * 32 + 255) / 256, 256>>>(bufC, W_o2, b_o2, out);
}

// round 8
// speedup vs baseline: 1.3404x; 1.3404x over previous
#include <cuda_runtime.h>
#include <cuda_bf16.h>
#include <cstdint>

#define NODES 100000
#define EDGES 640000
#define DIM   128
#define NDIN  239
#define KPAD_IN 256
#define NEG   0.01f
#define PITCH 40            // bf16 elems per smem row (80B, 16B-aligned, conflict-free)

// ---- scratch (__device__ globals; no allocs allowed) ----
__device__ float g_bufA[(size_t)NODES * DIM];
__device__ float g_bufB[(size_t)NODES * DIM];
__device__ float g_bufC[(size_t)NODES * DIM];
__device__ float g_deg[NODES];
__device__ float g_dinv[NODES];
__device__ float g_norm[EDGES];
// pre-transposed, bf16-split weights: B[n][k] = W[k][n]
__device__ __nv_bfloat16 g_Bin_hi[DIM * KPAD_IN];
__device__ __nv_bfloat16 g_Bin_lo[DIM * KPAD_IN];
__device__ __nv_bfloat16 g_Bg_hi[DIM * DIM];
__device__ __nv_bfloat16 g_Bg_lo[DIM * DIM];
__device__ __nv_bfloat16 g_Bo1_hi[DIM * DIM];
__device__ __nv_bfloat16 g_Bo1_lo[DIM * DIM];

// ---------------- helpers ----------------
__device__ __forceinline__ uint32_t smem_u32(const void* p) {
    uint32_t a;
    asm("{ .reg .u64 t; cvta.to.shared.u64 t, %1; cvt.u32.u64 %0, t; }" : "=r"(a) : "l"(p));
    return a;
}
__device__ __forceinline__ void ldsm4(uint32_t* r, uint32_t addr) {
    asm volatile("ldmatrix.sync.aligned.m8n8.x4.shared.b16 {%0,%1,%2,%3}, [%4];"
                 : "=r"(r[0]), "=r"(r[1]), "=r"(r[2]), "=r"(r[3]) : "r"(addr));
}
__device__ __forceinline__ void mma_bf16(float* c, const uint32_t* a,
                                         uint32_t b0, uint32_t b1) {
    asm volatile(
        "mma.sync.aligned.m16n8k16.row.col.f32.bf16.bf16.f32 "
        "{%0,%1,%2,%3}, {%4,%5,%6,%7}, {%8,%9}, {%0,%1,%2,%3};"
        : "+f"(c[0]), "+f"(c[1]), "+f"(c[2]), "+f"(c[3])
        : "r"(a[0]), "r"(a[1]), "r"(a[2]), "r"(a[3]), "r"(b0), "r"(b1));
}

// ---------------- graph structure + weight prep ----------------
__global__ void k_prep(const float* __restrict__ W_in, const float* __restrict__ W_g,
                       const float* __restrict__ W_o1) {
    int i = blockIdx.x * blockDim.x + threadIdx.x;
    if (i < NODES) g_deg[i] = 0.f;
    if (i < DIM * KPAD_IN) {              // W_in [239][128] -> Bin[n][256]
        int n = i / KPAD_IN, k = i % KPAD_IN;
        float v = (k < NDIN) ? W_in[k * DIM + n] : 0.f;
        __nv_bfloat16 h = __float2bfloat16(v);
        g_Bin_hi[i] = h;
        g_Bin_lo[i] = __float2bfloat16(v - __bfloat162float(h));
    }
    if (i < DIM * DIM) {                  // W_g, W_o1 [128][128] -> [n][128]
        int n = i / DIM, k = i % DIM;
        float v = W_g[k * DIM + n];
        __nv_bfloat16 h = __float2bfloat16(v);
        g_Bg_hi[i] = h;
        g_Bg_lo[i] = __float2bfloat16(v - __bfloat162float(h));
        float v2 = W_o1[k * DIM + n];
        __nv_bfloat16 h2 = __float2bfloat16(v2);
        g_Bo1_hi[i] = h2;
        g_Bo1_lo[i] = __float2bfloat16(v2 - __bfloat162float(h2));
    }
}

__global__ void k_deg(const int* __restrict__ ei) {
    int e = blockIdx.x * blockDim.x + threadIdx.x;
    if (e < EDGES) atomicAdd(&g_deg[ei[EDGES + e]], 1.f);
}
__global__ void k_dinv() {
    int i = blockIdx.x * blockDim.x + threadIdx.x;
    if (i < NODES) g_dinv[i] = rsqrtf(g_deg[i] + 1.f);
}
__global__ void k_norm(const int* __restrict__ ei) {
    int e = blockIdx.x * blockDim.x + threadIdx.x;
    if (e < EDGES) g_norm[e] = g_dinv[ei[e]] * g_dinv[ei[EDGES + e]];
}

// ================ HMMA GEMM: out[M,128] = A[M,K] @ W[K,128] ================
// Block 64x128, 256 thr (8 warps: 4m x 2n), warp 16x64. bf16 hi/lo 3-term split.
// LEAKY: out = leaky(acc + bias)
// CONV : out = acc (hw); agg = acc*dinv[row]^2 + bias  (self-loop fused)
template <bool LEAKY, bool CONV>
__global__ void __launch_bounds__(256)
k_mma(const float* __restrict__ A,
      const __nv_bfloat16* __restrict__ Bhi, const __nv_bfloat16* __restrict__ Blo,
      const float* __restrict__ bias,
      float* __restrict__ out, float* __restrict__ agg,
      int K, int KPAD) {
    __shared__ __align__(16) __nv_bfloat16 sAh[64 * PITCH];
    __shared__ __align__(16) __nv_bfloat16 sAl[64 * PITCH];
    __shared__ __align__(16) __nv_bfloat16 sBh[128 * PITCH];
    __shared__ __align__(16) __nv_bfloat16 sBl[128 * PITCH];

    int tid = threadIdx.x, wid = tid >> 5, lane = tid & 31;
    int warp_m = wid & 3, warp_n = wid >> 2;     // 4 x 2
    int m0 = warp_m * 16, n0w = warp_n * 64;
    int row0 = blockIdx.x * 64;

    float acc[8][4];
#pragma unroll
    for (int j = 0; j < 8; j++)
#pragma unroll
        for (int q = 0; q < 4; q++) acc[j][q] = 0.f;

    // ldmatrix per-thread base addresses: row = base + (lane&15), k-half = (lane>>4)*8
    uint32_t lrow = lane & 15;
    uint32_t kofB = (lane >> 4) * 16;            // bytes (8 elems * 2B)
    uint32_t adAh = smem_u32(sAh) + (m0 + lrow) * (PITCH * 2) + kofB;
    uint32_t adAl = smem_u32(sAl) + (m0 + lrow) * (PITCH * 2) + kofB;
    uint32_t adBh = smem_u32(sBh) + (n0w + lrow) * (PITCH * 2) + kofB;
    uint32_t adBl = smem_u32(sBl) + (n0w + lrow) * (PITCH * 2) + kofB;

    int nch = KPAD >> 5;                         // chunks of 32 k
    for (int ch = 0; ch < nch; ch++) {
        int k0 = ch << 5;
        // ---- stage A: 64 rows x 32 k fp32 -> hi/lo bf16 (warp per row, 8 rows each)
#pragma unroll
        for (int i = 0; i < 8; i++) {
            int r = wid + i * 8;
            int gr = row0 + r;
            if (gr >= NODES) gr = NODES - 1;     // clamp (results unused)
            int gc = k0 + lane;
            float v = (gc < K) ? A[(long)gr * K + gc] : 0.f;
            __nv_bfloat16 h = __float2bfloat16(v);
            sAh[r * PITCH + lane] = h;
            sAl[r * PITCH + lane] = __float2bfloat16(v - __bfloat162float(h));
        }
        // ---- stage B: 128 rows x 32 k bf16 hi/lo (2 rows per warp-pass)
#pragma unroll
        for (int p = 0; p < 8; p++) {
            int n = p * 16 + wid * 2 + (lane >> 4);
            int c2 = lane & 15;                  // b32 index (2 bf16)
            uint32_t vh = *(const uint32_t*)&Bhi[(long)n * KPAD + k0 + c2 * 2];
            uint32_t vl = *(const uint32_t*)&Blo[(long)n * KPAD + k0 + c2 * 2];
            *(uint32_t*)&sBh[n * PITCH + c2 * 2] = vh;
            *(uint32_t*)&sBl[n * PITCH + c2 * 2] = vl;
        }
        __syncthreads();

#pragma unroll
        for (int s = 0; s < 2; s++) {            // two k16 steps
            uint32_t kb = s * 32;                // 16 elems * 2B
            uint32_t ah[4], al[4];
            ldsm4(ah, adAh + kb);
            ldsm4(al, adAl + kb);
#pragma unroll
            for (int jp = 0; jp < 4; jp++) {     // pairs of n-tiles
                uint32_t bh[4], bl[4];
                uint32_t jo = jp * 16 * (PITCH * 2);
                ldsm4(bh, adBh + jo + kb);
                ldsm4(bl, adBl + jo + kb);
#pragma unroll
                for (int sub = 0; sub < 2; sub++) {
                    int j = jp * 2 + sub;
                    mma_bf16(acc[j], ah, bh[sub], bh[2 + sub]);  // hi*hi
                    mma_bf16(acc[j], al, bh[sub], bh[2 + sub]);  // lo*hi
                    mma_bf16(acc[j], ah, bl[sub], bl[2 + sub]);  // hi*lo
                }
            }
        }
        __syncthreads();
    }

    // ---- epilogue: thread holds rows (m0 + lane/4, +8), cols n0w + j*8 + (lane%4)*2
    int mr = lane >> 2;
    int c0 = (lane & 3) * 2;
#pragma unroll
    for (int j = 0; j < 8; j++) {
        int n = n0w + j * 8 + c0;
        float2 b2 = *(const float2*)&bias[n];
#pragma unroll
        for (int h = 0; h < 2; h++) {
            int r = row0 + m0 + mr + h * 8;
            if (r >= NODES) continue;
            float vx = acc[j][h * 2], vy = acc[j][h * 2 + 1];
            long base = (long)r * DIM + n;
            if (CONV) {
                *(float2*)&out[base] = make_float2(vx, vy);   // hw for scatter
                float d = g_dinv[r];
                float s = d * d;
                *(float2*)&agg[base] =
                    make_float2(fmaf(vx, s, b2.x), fmaf(vy, s, b2.y));
            } else {
                vx += b2.x; vy += b2.y;
                if (LEAKY) {
                    vx = fmaxf(vx, NEG * vx);
                    vy = fmaxf(vy, NEG * vy);
                }
                *(float2*)&out[base] = make_float2(vx, vy);
            }
        }
    }
}

// ---------------- edge scatter (R4-proven): agg[dst] += hw[src]*norm ----------------
__global__ void k_scatter(const int* __restrict__ ei,
                          const float* __restrict__ hw,
                          float* __restrict__ agg) {
    int idx = blockIdx.x * blockDim.x + threadIdx.x;
    int e = idx >> 5;
    int c = idx & 31;
    if (e >= EDGES) return;
    int src = ei[e];
    int dst = ei[EDGES + e];
    float n = g_norm[e];
    float4 v = *(const float4*)&hw[(long)src * 128 + c * 4];
    float* p = &agg[(long)dst * 128 + c * 4];
    asm volatile("red.global.add.v4.f32 [%0], {%1, %2, %3, %4};"
                 :: "l"(p), "f"(v.x * n), "f"(v.y * n), "f"(v.z * n), "f"(v.w * n)
                 : "memory");
}

// ---------------- final projection: out[M,2] = h[M,128] @ W[128,2] + b ----------------
__global__ void k_out(const float* __restrict__ h, const float* __restrict__ W,
                      const float* __restrict__ b, float* __restrict__ out) {
    __shared__ float ws[256];
    int tid = threadIdx.x;
    if (tid < 256) ws[tid] = W[tid];
    __syncthreads();
    int warp = (blockIdx.x * blockDim.x + tid) >> 5;
    int lane = tid & 31;
    if (warp >= NODES) return;
    float4 v = *(const float4*)&h[(long)warp * 128 + lane * 4];
    int k = lane * 4;
    float s0 = v.x * ws[(k + 0) * 2] + v.y * ws[(k + 1) * 2] +
               v.z * ws[(k + 2) * 2] + v.w * ws[(k + 3) * 2];
    float s1 = v.x * ws[(k + 0) * 2 + 1] + v.y * ws[(k + 1) * 2 + 1] +
               v.z * ws[(k + 2) * 2 + 1] + v.w * ws[(k + 3) * 2 + 1];
#pragma unroll
    for (int o = 16; o; o >>= 1) {
        s0 += __shfl_xor_sync(0xFFFFFFFFu, s0, o);
        s1 += __shfl_xor_sync(0xFFFFFFFFu, s1, o);
    }
    if (lane == 0) {
        out[(long)warp * 2 + 0] = s0 + b[0];
        out[(long)warp * 2 + 1] = s1 + b[1];
    }
}

// ---------------- launch ----------------
extern "C" void kernel_launch(void* const* d_in, const int* in_sizes, int n_in,
                              void* d_out, int out_size) {
    int ix, iei, iwin, ibin, iwg, ibg, iwo1, ibo1, iwo2, ibo2;
    if (in_sizes[0] == 16384) {          // alphabetical (hedge)
        iwg = 0; iwin = 1; iwo1 = 2; iwo2 = 3;
        ibg = 4; ibin = 5; ibo1 = 6; ibo2 = 7;
        iei = 8; ix = 10;
    } else {                              // dict / insertion order
        ix = 0; iei = 1;
        iwin = 3; ibin = 4; iwg = 5; ibg = 6;
        iwo1 = 7; ibo1 = 8; iwo2 = 9; ibo2 = 10;
    }

    const float* x    = (const float*)d_in[ix];
    const int*   ei   = (const int*)d_in[iei];   // int32 (JAX x64 disabled)
    const float* W_in = (const float*)d_in[iwin];
    const float* b_in = (const float*)d_in[ibin];
    const float* W_g  = (const float*)d_in[iwg];
    const float* b_g  = (const float*)d_in[ibg];
    const float* W_o1 = (const float*)d_in[iwo1];
    const float* b_o1 = (const float*)d_in[ibo1];
    const float* W_o2 = (const float*)d_in[iwo2];
    const float* b_o2 = (const float*)d_in[ibo2];
    float* out = (float*)d_out;

    float *bufA, *bufB, *bufC;
    cudaGetSymbolAddress((void**)&bufA, g_bufA);
    cudaGetSymbolAddress((void**)&bufB, g_bufB);
    cudaGetSymbolAddress((void**)&bufC, g_bufC);
    __nv_bfloat16 *Bin_hi, *Bin_lo, *Bg_hi, *Bg_lo, *Bo1_hi, *Bo1_lo;
    cudaGetSymbolAddress((void**)&Bin_hi, g_Bin_hi);
    cudaGetSymbolAddress((void**)&Bin_lo, g_Bin_lo);
    cudaGetSymbolAddress((void**)&Bg_hi, g_Bg_hi);
    cudaGetSymbolAddress((void**)&Bg_lo, g_Bg_lo);
    cudaGetSymbolAddress((void**)&Bo1_hi, g_Bo1_hi);
    cudaGetSymbolAddress((void**)&Bo1_lo, g_Bo1_lo);

    int gemm_grid = (NODES + 63) / 64;            // 1563
    int scat_grid = (EDGES * 32 + 255) / 256;

    // 0: zero deg + split/transpose weights
    k_prep<<<(NODES + 255) / 256, 256>>>(W_in, W_g, W_o1);
    // 1-2: degree + dinv
    k_deg<<<(EDGES + 255) / 256, 256>>>(ei);
    k_dinv<<<(NODES + 255) / 256, 256>>>();
    // 3 (profiled): h0 = leaky(x @ W_in + b_in) -> bufA   [K=239, KPAD=256]
    k_mma<true, false><<<gemm_grid, 256>>>(x, Bin_hi, Bin_lo, b_in, bufA, nullptr,
                                           NDIN, KPAD_IN);
    // 4: edge norms
    k_norm<<<(EDGES + 255) / 256, 256>>>(ei);

    // conv1: hw -> bufB ; agg(self+bias) -> bufC ; scatter into bufC
    k_mma<false, true><<<gemm_grid, 256>>>(bufA, Bg_hi, Bg_lo, b_g, bufB, bufC,
                                           DIM, DIM);
    k_scatter<<<scat_grid, 256>>>(ei, bufB, bufC);

    // conv2: hw -> bufB ; agg -> bufA ; scatter into bufA
    k_mma<false, true><<<gemm_grid, 256>>>(bufC, Bg_hi, Bg_lo, b_g, bufB, bufA,
                                           DIM, DIM);
    k_scatter<<<scat_grid, 256>>>(ei, bufB, bufA);

    // h3 = leaky(bufA @ W_o1 + b_o1) -> bufC
    k_mma<true, false><<<gemm_grid, 256>>>(bufA, Bo1_hi, Bo1_lo, b_o1, bufC, nullptr,
                                           DIM, DIM);

    // out = bufC @ W_o2 + b_o2
    k_out<<<(NODES * 32 + 255) / 256, 256>>>(bufC, W_o2, b_o2, out);
}

// round 9
// speedup vs baseline: 1.6951x; 1.2646x over previous
#include <cuda_runtime.h>
#include <cuda_bf16.h>
#include <cstdint>

#define NODES 100000
#define EDGES 640000
#define DIM   128
#define NDIN  239
#define KPAD_IN 256
#define NEG   0.01f
#define PITCH 40            // bf16 elems per smem row (80B, 16B-aligned, conflict-free)

// ---- scratch (__device__ globals; no allocs allowed) ----
__device__ float g_bufA[(size_t)NODES * DIM];
__device__ float g_bufB[(size_t)NODES * DIM];
__device__ float g_bufC[(size_t)NODES * DIM];
__device__ float g_deg[NODES];
__device__ float g_dinv[NODES];
__device__ float g_norm[EDGES];
// pre-transposed, bf16-split weights: B[n][k] = W[k][n]
__device__ __nv_bfloat16 g_Bin_hi[DIM * KPAD_IN];
__device__ __nv_bfloat16 g_Bin_lo[DIM * KPAD_IN];
__device__ __nv_bfloat16 g_Bg_hi[DIM * DIM];
__device__ __nv_bfloat16 g_Bg_lo[DIM * DIM];
__device__ __nv_bfloat16 g_Bo1_hi[DIM * DIM];
__device__ __nv_bfloat16 g_Bo1_lo[DIM * DIM];

// ---------------- helpers ----------------
__device__ __forceinline__ uint32_t smem_u32(const void* p) {
    uint32_t a;
    asm("{ .reg .u64 t; cvta.to.shared.u64 t, %1; cvt.u32.u64 %0, t; }" : "=r"(a) : "l"(p));
    return a;
}
__device__ __forceinline__ void ldsm4(uint32_t* r, uint32_t addr) {
    asm volatile("ldmatrix.sync.aligned.m8n8.x4.shared.b16 {%0,%1,%2,%3}, [%4];"
                 : "=r"(r[0]), "=r"(r[1]), "=r"(r[2]), "=r"(r[3]) : "r"(addr));
}
__device__ __forceinline__ void mma_bf16(float* c, const uint32_t* a,
                                         uint32_t b0, uint32_t b1) {
    asm volatile(
        "mma.sync.aligned.m16n8k16.row.col.f32.bf16.bf16.f32 "
        "{%0,%1,%2,%3}, {%4,%5,%6,%7}, {%8,%9}, {%0,%1,%2,%3};"
        : "+f"(c[0]), "+f"(c[1]), "+f"(c[2]), "+f"(c[3])
        : "r"(a[0]), "r"(a[1]), "r"(a[2]), "r"(a[3]), "r"(b0), "r"(b1));
}

// ---------------- graph structure + weight prep ----------------
__global__ void k_prep(const float* __restrict__ W_in, const float* __restrict__ W_g,
                       const float* __restrict__ W_o1) {
    int i = blockIdx.x * blockDim.x + threadIdx.x;
    if (i < NODES) g_deg[i] = 0.f;
    if (i < DIM * KPAD_IN) {              // W_in [239][128] -> Bin[n][256]
        int n = i / KPAD_IN, k = i % KPAD_IN;
        float v = (k < NDIN) ? W_in[k * DIM + n] : 0.f;
        __nv_bfloat16 h = __float2bfloat16(v);
        g_Bin_hi[i] = h;
        g_Bin_lo[i] = __float2bfloat16(v - __bfloat162float(h));
    }
    if (i < DIM * DIM) {                  // W_g, W_o1 [128][128] -> [n][128]
        int n = i / DIM, k = i % DIM;
        float v = W_g[k * DIM + n];
        __nv_bfloat16 h = __float2bfloat16(v);
        g_Bg_hi[i] = h;
        g_Bg_lo[i] = __float2bfloat16(v - __bfloat162float(h));
        float v2 = W_o1[k * DIM + n];
        __nv_bfloat16 h2 = __float2bfloat16(v2);
        g_Bo1_hi[i] = h2;
        g_Bo1_lo[i] = __float2bfloat16(v2 - __bfloat162float(h2));
    }
}

__global__ void k_deg(const int* __restrict__ ei) {
    int e = blockIdx.x * blockDim.x + threadIdx.x;
    if (e < EDGES) atomicAdd(&g_deg[ei[EDGES + e]], 1.f);
}
__global__ void k_dinv() {
    int i = blockIdx.x * blockDim.x + threadIdx.x;
    if (i < NODES) g_dinv[i] = rsqrtf(g_deg[i] + 1.f);
}
__global__ void k_norm(const int* __restrict__ ei) {
    int e = blockIdx.x * blockDim.x + threadIdx.x;
    if (e < EDGES) g_norm[e] = g_dinv[ei[e]] * g_dinv[ei[EDGES + e]];
}

// ================ HMMA GEMM: out[M,128] = A[M,K] @ W[K,128] ================
// Block 64x128, 256 thr (8 warps: 4m x 2n), warp 16x64. bf16 hi/lo 3-term split.
// __launch_bounds__(256, 2): cap regs at 128 -> 2 CTAs/SM (R8 had 137 regs, 1 CTA/SM).
// LEAKY: out = leaky(acc + bias)
// CONV : out = acc (hw); agg = acc*dinv[row]^2 + bias  (self-loop fused)
template <bool LEAKY, bool CONV>
__global__ void __launch_bounds__(256, 2)
k_mma(const float* __restrict__ A,
      const __nv_bfloat16* __restrict__ Bhi, const __nv_bfloat16* __restrict__ Blo,
      const float* __restrict__ bias,
      float* __restrict__ out, float* __restrict__ agg,
      int K, int KPAD) {
    __shared__ __align__(16) __nv_bfloat16 sAh[64 * PITCH];
    __shared__ __align__(16) __nv_bfloat16 sAl[64 * PITCH];
    __shared__ __align__(16) __nv_bfloat16 sBh[128 * PITCH];
    __shared__ __align__(16) __nv_bfloat16 sBl[128 * PITCH];

    int tid = threadIdx.x, wid = tid >> 5, lane = tid & 31;
    int warp_m = wid & 3, warp_n = wid >> 2;     // 4 x 2
    int m0 = warp_m * 16, n0w = warp_n * 64;
    int row0 = blockIdx.x * 64;

    float acc[8][4];
#pragma unroll
    for (int j = 0; j < 8; j++)
#pragma unroll
        for (int q = 0; q < 4; q++) acc[j][q] = 0.f;

    // ldmatrix per-thread base addresses: row = base + (lane&15), k-half = (lane>>4)*8
    uint32_t lrow = lane & 15;
    uint32_t kofB = (lane >> 4) * 16;            // bytes (8 elems * 2B)
    uint32_t adAh = smem_u32(sAh) + (m0 + lrow) * (PITCH * 2) + kofB;
    uint32_t adAl = smem_u32(sAl) + (m0 + lrow) * (PITCH * 2) + kofB;
    uint32_t adBh = smem_u32(sBh) + (n0w + lrow) * (PITCH * 2) + kofB;
    uint32_t adBl = smem_u32(sBl) + (n0w + lrow) * (PITCH * 2) + kofB;

    int nch = KPAD >> 5;                         // chunks of 32 k
    for (int ch = 0; ch < nch; ch++) {
        int k0 = ch << 5;
        // ---- stage A: 64 rows x 32 k fp32 -> hi/lo bf16 (warp per row, 8 rows each)
#pragma unroll
        for (int i = 0; i < 8; i++) {
            int r = wid + i * 8;
            int gr = row0 + r;
            if (gr >= NODES) gr = NODES - 1;     // clamp (results unused)
            int gc = k0 + lane;
            float v = (gc < K) ? A[(long)gr * K + gc] : 0.f;
            __nv_bfloat16 h = __float2bfloat16(v);
            sAh[r * PITCH + lane] = h;
            sAl[r * PITCH + lane] = __float2bfloat16(v - __bfloat162float(h));
        }
        // ---- stage B: 128 rows x 32 k bf16 hi/lo (2 rows per warp-pass)
#pragma unroll
        for (int p = 0; p < 8; p++) {
            int n = p * 16 + wid * 2 + (lane >> 4);
            int c2 = lane & 15;                  // b32 index (2 bf16)
            uint32_t vh = *(const uint32_t*)&Bhi[(long)n * KPAD + k0 + c2 * 2];
            uint32_t vl = *(const uint32_t*)&Blo[(long)n * KPAD + k0 + c2 * 2];
            *(uint32_t*)&sBh[n * PITCH + c2 * 2] = vh;
            *(uint32_t*)&sBl[n * PITCH + c2 * 2] = vl;
        }
        __syncthreads();

#pragma unroll
        for (int s = 0; s < 2; s++) {            // two k16 steps
            uint32_t kb = s * 32;                // 16 elems * 2B
            uint32_t ah[4], al[4];
            ldsm4(ah, adAh + kb);
            ldsm4(al, adAl + kb);
#pragma unroll
            for (int jp = 0; jp < 4; jp++) {     // pairs of n-tiles
                uint32_t bh[4], bl[4];
                uint32_t jo = jp * 16 * (PITCH * 2);
                ldsm4(bh, adBh + jo + kb);
                ldsm4(bl, adBl + jo + kb);
#pragma unroll
                for (int sub = 0; sub < 2; sub++) {
                    int j = jp * 2 + sub;
                    mma_bf16(acc[j], ah, bh[sub], bh[2 + sub]);  // hi*hi
                    mma_bf16(acc[j], al, bh[sub], bh[2 + sub]);  // lo*hi
                    mma_bf16(acc[j], ah, bl[sub], bl[2 + sub]);  // hi*lo
                }
            }
        }
        __syncthreads();
    }

    // ---- epilogue: thread holds rows (m0 + lane/4, +8), cols n0w + j*8 + (lane%4)*2
    int mr = lane >> 2;
    int c0 = (lane & 3) * 2;
#pragma unroll
    for (int j = 0; j < 8; j++) {
        int n = n0w + j * 8 + c0;
        float2 b2 = *(const float2*)&bias[n];
#pragma unroll
        for (int h = 0; h < 2; h++) {
            int r = row0 + m0 + mr + h * 8;
            if (r >= NODES) continue;
            float vx = acc[j][h * 2], vy = acc[j][h * 2 + 1];
            long base = (long)r * DIM + n;
            if (CONV) {
                *(float2*)&out[base] = make_float2(vx, vy);   // hw for scatter
                float d = g_dinv[r];
                float s = d * d;
                *(float2*)&agg[base] =
                    make_float2(fmaf(vx, s, b2.x), fmaf(vy, s, b2.y));
            } else {
                vx += b2.x; vy += b2.y;
                if (LEAKY) {
                    vx = fmaxf(vx, NEG * vx);
                    vy = fmaxf(vy, NEG * vy);
                }
                *(float2*)&out[base] = make_float2(vx, vy);
            }
        }
    }
}

// ---------------- edge scatter (R4-proven): agg[dst] += hw[src]*norm ----------------
__global__ void k_scatter(const int* __restrict__ ei,
                          const float* __restrict__ hw,
                          float* __restrict__ agg) {
    int idx = blockIdx.x * blockDim.x + threadIdx.x;
    int e = idx >> 5;
    int c = idx & 31;
    if (e >= EDGES) return;
    int src = ei[e];
    int dst = ei[EDGES + e];
    float n = g_norm[e];
    float4 v = *(const float4*)&hw[(long)src * 128 + c * 4];
    float* p = &agg[(long)dst * 128 + c * 4];
    asm volatile("red.global.add.v4.f32 [%0], {%1, %2, %3, %4};"
                 :: "l"(p), "f"(v.x * n), "f"(v.y * n), "f"(v.z * n), "f"(v.w * n)
                 : "memory");
}

// ---------------- final projection: out[M,2] = h[M,128] @ W[128,2] + b ----------------
__global__ void k_out(const float* __restrict__ h, const float* __restrict__ W,
                      const float* __restrict__ b, float* __restrict__ out) {
    __shared__ float ws[256];
    int tid = threadIdx.x;
    if (tid < 256) ws[tid] = W[tid];
    __syncthreads();
    int warp = (blockIdx.x * blockDim.x + tid) >> 5;
    int lane = tid & 31;
    if (warp >= NODES) return;
    float4 v = *(const float4*)&h[(long)warp * 128 + lane * 4];
    int k = lane * 4;
    float s0 = v.x * ws[(k + 0) * 2] + v.y * ws[(k + 1) * 2] +
               v.z * ws[(k + 2) * 2] + v.w * ws[(k + 3) * 2];
    float s1 = v.x * ws[(k + 0) * 2 + 1] + v.y * ws[(k + 1) * 2 + 1] +
               v.z * ws[(k + 2) * 2 + 1] + v.w * ws[(k + 3) * 2 + 1];
#pragma unroll
    for (int o = 16; o; o >>= 1) {
        s0 += __shfl_xor_sync(0xFFFFFFFFu, s0, o);
        s1 += __shfl_xor_sync(0xFFFFFFFFu, s1, o);
    }
    if (lane == 0) {
        out[(long)warp * 2 + 0] = s0 + b[0];
        out[(long)warp * 2 + 1] = s1 + b[1];
    }
}

// ---------------- launch ----------------
extern "C" void kernel_launch(void* const* d_in, const int* in_sizes, int n_in,
                              void* d_out, int out_size) {
    int ix, iei, iwin, ibin, iwg, ibg, iwo1, ibo1, iwo2, ibo2;
    if (in_sizes[0] == 16384) {          // alphabetical (hedge)
        iwg = 0; iwin = 1; iwo1 = 2; iwo2 = 3;
        ibg = 4; ibin = 5; ibo1 = 6; ibo2 = 7;
        iei = 8; ix = 10;
    } else {                              // dict / insertion order
        ix = 0; iei = 1;
        iwin = 3; ibin = 4; iwg = 5; ibg = 6;
        iwo1 = 7; ibo1 = 8; iwo2 = 9; ibo2 = 10;
    }

    const float* x    = (const float*)d_in[ix];
    const int*   ei   = (const int*)d_in[iei];   // int32 (JAX x64 disabled)
    const float* W_in = (const float*)d_in[iwin];
    const float* b_in = (const float*)d_in[ibin];
    const float* W_g  = (const float*)d_in[iwg];
    const float* b_g  = (const float*)d_in[ibg];
    const float* W_o1 = (const float*)d_in[iwo1];
    const float* b_o1 = (const float*)d_in[ibo1];
    const float* W_o2 = (const float*)d_in[iwo2];
    const float* b_o2 = (const float*)d_in[ibo2];
    float* out = (float*)d_out;

    float *bufA, *bufB, *bufC;
    cudaGetSymbolAddress((void**)&bufA, g_bufA);
    cudaGetSymbolAddress((void**)&bufB, g_bufB);
    cudaGetSymbolAddress((void**)&bufC, g_bufC);
    __nv_bfloat16 *Bin_hi, *Bin_lo, *Bg_hi, *Bg_lo, *Bo1_hi, *Bo1_lo;
    cudaGetSymbolAddress((void**)&Bin_hi, g_Bin_hi);
    cudaGetSymbolAddress((void**)&Bin_lo, g_Bin_lo);
    cudaGetSymbolAddress((void**)&Bg_hi, g_Bg_hi);
    cudaGetSymbolAddress((void**)&Bg_lo, g_Bg_lo);
    cudaGetSymbolAddress((void**)&Bo1_hi, g_Bo1_hi);
    cudaGetSymbolAddress((void**)&Bo1_lo, g_Bo1_lo);

    int gemm_grid = (NODES + 63) / 64;            // 1563
    int scat_grid = (EDGES * 32 + 255) / 256;

    // 0: zero deg + split/transpose weights
    k_prep<<<(NODES + 255) / 256, 256>>>(W_in, W_g, W_o1);
    // 1-2: degree + dinv
    k_deg<<<(EDGES + 255) / 256, 256>>>(ei);
    k_dinv<<<(NODES + 255) / 256, 256>>>();
    // 3 (profiled): h0 = leaky(x @ W_in + b_in) -> bufA   [K=239, KPAD=256]
    k_mma<true, false><<<gemm_grid, 256>>>(x, Bin_hi, Bin_lo, b_in, bufA, nullptr,
                                           NDIN, KPAD_IN);
    // 4: edge norms
    k_norm<<<(EDGES + 255) / 256, 256>>>(ei);

    // conv1: hw -> bufB ; agg(self+bias) -> bufC ; scatter into bufC
    k_mma<false, true><<<gemm_grid, 256>>>(bufA, Bg_hi, Bg_lo, b_g, bufB, bufC,
                                           DIM, DIM);
    k_scatter<<<scat_grid, 256>>>(ei, bufB, bufC);

    // conv2: hw -> bufB ; agg -> bufA ; scatter into bufA
    k_mma<false, true><<<gemm_grid, 256>>>(bufC, Bg_hi, Bg_lo, b_g, bufB, bufA,
                                           DIM, DIM);
    k_scatter<<<scat_grid, 256>>>(ei, bufB, bufA);

    // h3 = leaky(bufA @ W_o1 + b_o1) -> bufC
    k_mma<true, false><<<gemm_grid, 256>>>(bufA, Bo1_hi, Bo1_lo, b_o1, bufC, nullptr,
                                           DIM, DIM);

    // out = bufC @ W_o2 + b_o2
    k_out<<<(NODES * 32 + 255) / 256, 256>>>(bufC, W_o2, b_o2, out);
}

// round 10
// speedup vs baseline: 1.8451x; 1.0885x over previous
#include <cuda_runtime.h>
#include <cuda_bf16.h>
#include <cstdint>

#define NODES 100000
#define EDGES 640000
#define DIM   128
#define NDIN  239
#define KPAD_IN 256
#define NEG   0.01f
#define PITCH 40            // bf16 elems per smem row (80B, 16B-aligned, conflict-free)

// ---- scratch (__device__ globals; no allocs allowed) ----
__device__ float g_bufA[(size_t)NODES * DIM];
__device__ float g_bufB[(size_t)NODES * DIM];
__device__ float g_bufC[(size_t)NODES * DIM];
__device__ float g_deg[NODES];
__device__ float g_dinv[NODES];
__device__ float g_norm[EDGES];
// pre-transposed, bf16-split weights: B[n][k] = W[k][n]
__device__ __nv_bfloat16 g_Bin_hi[DIM * KPAD_IN];
__device__ __nv_bfloat16 g_Bin_lo[DIM * KPAD_IN];
__device__ __nv_bfloat16 g_Bg_hi[DIM * DIM];
__device__ __nv_bfloat16 g_Bg_lo[DIM * DIM];
__device__ __nv_bfloat16 g_Bo1_hi[DIM * DIM];
__device__ __nv_bfloat16 g_Bo1_lo[DIM * DIM];

// ---------------- helpers ----------------
__device__ __forceinline__ uint32_t smem_u32(const void* p) {
    uint32_t a;
    asm("{ .reg .u64 t; cvta.to.shared.u64 t, %1; cvt.u32.u64 %0, t; }" : "=r"(a) : "l"(p));
    return a;
}
__device__ __forceinline__ void ldsm4(uint32_t* r, uint32_t addr) {
    asm volatile("ldmatrix.sync.aligned.m8n8.x4.shared.b16 {%0,%1,%2,%3}, [%4];"
                 : "=r"(r[0]), "=r"(r[1]), "=r"(r[2]), "=r"(r[3]) : "r"(addr));
}
__device__ __forceinline__ void mma_bf16(float* c, const uint32_t* a,
                                         uint32_t b0, uint32_t b1) {
    asm volatile(
        "mma.sync.aligned.m16n8k16.row.col.f32.bf16.bf16.f32 "
        "{%0,%1,%2,%3}, {%4,%5,%6,%7}, {%8,%9}, {%0,%1,%2,%3};"
        : "+f"(c[0]), "+f"(c[1]), "+f"(c[2]), "+f"(c[3])
        : "r"(a[0]), "r"(a[1]), "r"(a[2]), "r"(a[3]), "r"(b0), "r"(b1));
}

// ---------------- graph structure + weight prep ----------------
__global__ void k_prep(const float* __restrict__ W_in, const float* __restrict__ W_g,
                       const float* __restrict__ W_o1) {
    int i = blockIdx.x * blockDim.x + threadIdx.x;
    if (i < NODES) g_deg[i] = 0.f;
    if (i < DIM * KPAD_IN) {              // W_in [239][128] -> Bin[n][256]
        int n = i / KPAD_IN, k = i % KPAD_IN;
        float v = (k < NDIN) ? W_in[k * DIM + n] : 0.f;
        __nv_bfloat16 h = __float2bfloat16(v);
        g_Bin_hi[i] = h;
        g_Bin_lo[i] = __float2bfloat16(v - __bfloat162float(h));
    }
    if (i < DIM * DIM) {                  // W_g, W_o1 [128][128] -> [n][128]
        int n = i / DIM, k = i % DIM;
        float v = W_g[k * DIM + n];
        __nv_bfloat16 h = __float2bfloat16(v);
        g_Bg_hi[i] = h;
        g_Bg_lo[i] = __float2bfloat16(v - __bfloat162float(h));
        float v2 = W_o1[k * DIM + n];
        __nv_bfloat16 h2 = __float2bfloat16(v2);
        g_Bo1_hi[i] = h2;
        g_Bo1_lo[i] = __float2bfloat16(v2 - __bfloat162float(h2));
    }
}

__global__ void k_deg(const int* __restrict__ ei) {
    int e = blockIdx.x * blockDim.x + threadIdx.x;
    if (e < EDGES) atomicAdd(&g_deg[ei[EDGES + e]], 1.f);
}
__global__ void k_dinv() {
    int i = blockIdx.x * blockDim.x + threadIdx.x;
    if (i < NODES) g_dinv[i] = rsqrtf(g_deg[i] + 1.f);
}
__global__ void k_norm(const int* __restrict__ ei) {
    int e = blockIdx.x * blockDim.x + threadIdx.x;
    if (e < EDGES) g_norm[e] = g_dinv[ei[e]] * g_dinv[ei[EDGES + e]];
}

// ================ HMMA GEMM: out[M,128] = A[M,K] @ W[K,128] ================
// Block tile 128x128, 256 thr (8 warps: 4m x 2n), warp tile 32x64.
// bf16 hi/lo 3-term split (hh + lh + hl). 12 ldsm.x4 -> 48 MMAs per k16.
// LEAKY: out = leaky(acc + bias)
// CONV : out = acc (hw); agg = acc*dinv[row]^2 + bias  (self-loop fused)
template <bool LEAKY, bool CONV>
__global__ void __launch_bounds__(256, 2)
k_mma(const float* __restrict__ A,
      const __nv_bfloat16* __restrict__ Bhi, const __nv_bfloat16* __restrict__ Blo,
      const float* __restrict__ bias,
      float* __restrict__ out, float* __restrict__ agg,
      int K, int KPAD) {
    __shared__ __align__(16) __nv_bfloat16 sAh[128 * PITCH];
    __shared__ __align__(16) __nv_bfloat16 sAl[128 * PITCH];
    __shared__ __align__(16) __nv_bfloat16 sBh[128 * PITCH];
    __shared__ __align__(16) __nv_bfloat16 sBl[128 * PITCH];

    int tid = threadIdx.x, wid = tid >> 5, lane = tid & 31;
    int warp_m = wid & 3, warp_n = wid >> 2;     // 4m x 2n
    int m0 = warp_m * 32, n0w = warp_n * 64;
    int row0 = blockIdx.x * 128;

    float acc[2][8][4];
#pragma unroll
    for (int mt = 0; mt < 2; mt++)
#pragma unroll
        for (int j = 0; j < 8; j++)
#pragma unroll
            for (int q = 0; q < 4; q++) acc[mt][j][q] = 0.f;

    // ldmatrix per-thread base: row = (lane&15), k-half = (lane>>4)*8 elems
    uint32_t lrow = lane & 15;
    uint32_t kofB = (lane >> 4) * 16;            // bytes
    uint32_t adAh = smem_u32(sAh) + (m0 + lrow) * (PITCH * 2) + kofB;
    uint32_t adAl = smem_u32(sAl) + (m0 + lrow) * (PITCH * 2) + kofB;
    uint32_t adBh = smem_u32(sBh) + (n0w + lrow) * (PITCH * 2) + kofB;
    uint32_t adBl = smem_u32(sBl) + (n0w + lrow) * (PITCH * 2) + kofB;
    const uint32_t MT_OFF = 16 * (PITCH * 2);

    int nch = KPAD >> 5;                         // chunks of 32 k
    for (int ch = 0; ch < nch; ch++) {
        int k0 = ch << 5;
        // ---- stage A: 128 rows x 32 k fp32 -> hi/lo bf16 (16 rows per warp)
#pragma unroll
        for (int i = 0; i < 16; i++) {
            int r = wid + i * 8;
            int gr = row0 + r;
            if (gr >= NODES) gr = NODES - 1;     // clamp (results unused)
            int gc = k0 + lane;
            float v = (gc < K) ? A[(long)gr * K + gc] : 0.f;
            __nv_bfloat16 h = __float2bfloat16(v);
            sAh[r * PITCH + lane] = h;
            sAl[r * PITCH + lane] = __float2bfloat16(v - __bfloat162float(h));
        }
        // ---- stage B: 128 n-rows x 32 k bf16 hi/lo
#pragma unroll
        for (int p = 0; p < 8; p++) {
            int n = p * 16 + wid * 2 + (lane >> 4);
            int c2 = lane & 15;                  // b32 index (2 bf16)
            uint32_t vh = *(const uint32_t*)&Bhi[(long)n * KPAD + k0 + c2 * 2];
            uint32_t vl = *(const uint32_t*)&Blo[(long)n * KPAD + k0 + c2 * 2];
            *(uint32_t*)&sBh[n * PITCH + c2 * 2] = vh;
            *(uint32_t*)&sBl[n * PITCH + c2 * 2] = vl;
        }
        __syncthreads();

#pragma unroll
        for (int s = 0; s < 2; s++) {            // two k16 steps
            uint32_t kb = s * 32;                // bytes (16 elems)
            uint32_t ah[2][4], al[2][4];
            ldsm4(ah[0], adAh + kb);
            ldsm4(al[0], adAl + kb);
            ldsm4(ah[1], adAh + MT_OFF + kb);
            ldsm4(al[1], adAl + MT_OFF + kb);
#pragma unroll
            for (int jp = 0; jp < 4; jp++) {     // pairs of n8-tiles
                uint32_t bh[4], bl[4];
                uint32_t jo = jp * 16 * (PITCH * 2);
                ldsm4(bh, adBh + jo + kb);
                ldsm4(bl, adBl + jo + kb);
#pragma unroll
                for (int mt = 0; mt < 2; mt++) {
#pragma unroll
                    for (int sub = 0; sub < 2; sub++) {
                        int j = jp * 2 + sub;
                        mma_bf16(acc[mt][j], ah[mt], bh[sub], bh[2 + sub]); // hi*hi
                        mma_bf16(acc[mt][j], al[mt], bh[sub], bh[2 + sub]); // lo*hi
                        mma_bf16(acc[mt][j], ah[mt], bl[sub], bl[2 + sub]); // hi*lo
                    }
                }
            }
        }
        __syncthreads();
    }

    // ---- epilogue: rows m0 + mt*16 + (lane>>2) + h*8; cols n0w + j*8 + (lane&3)*2
    int mr = lane >> 2;
    int c0 = (lane & 3) * 2;
#pragma unroll
    for (int mt = 0; mt < 2; mt++) {
#pragma unroll
        for (int j = 0; j < 8; j++) {
            int n = n0w + j * 8 + c0;
            float2 b2 = *(const float2*)&bias[n];
#pragma unroll
            for (int h = 0; h < 2; h++) {
                int r = row0 + m0 + mt * 16 + mr + h * 8;
                if (r >= NODES) continue;
                float vx = acc[mt][j][h * 2], vy = acc[mt][j][h * 2 + 1];
                long base = (long)r * DIM + n;
                if (CONV) {
                    *(float2*)&out[base] = make_float2(vx, vy);   // hw for scatter
                    float d = g_dinv[r];
                    float s = d * d;
                    *(float2*)&agg[base] =
                        make_float2(fmaf(vx, s, b2.x), fmaf(vy, s, b2.y));
                } else {
                    vx += b2.x; vy += b2.y;
                    if (LEAKY) {
                        vx = fmaxf(vx, NEG * vx);
                        vy = fmaxf(vy, NEG * vy);
                    }
                    *(float2*)&out[base] = make_float2(vx, vy);
                }
            }
        }
    }
}

// ---------------- edge scatter (R4-proven): agg[dst] += hw[src]*norm ----------------
__global__ void k_scatter(const int* __restrict__ ei,
                          const float* __restrict__ hw,
                          float* __restrict__ agg) {
    int idx = blockIdx.x * blockDim.x + threadIdx.x;
    int e = idx >> 5;
    int c = idx & 31;
    if (e >= EDGES) return;
    int src = ei[e];
    int dst = ei[EDGES + e];
    float n = g_norm[e];
    float4 v = *(const float4*)&hw[(long)src * 128 + c * 4];
    float* p = &agg[(long)dst * 128 + c * 4];
    asm volatile("red.global.add.v4.f32 [%0], {%1, %2, %3, %4};"
                 :: "l"(p), "f"(v.x * n), "f"(v.y * n), "f"(v.z * n), "f"(v.w * n)
                 : "memory");
}

// ---------------- final projection: out[M,2] = h[M,128] @ W[128,2] + b ----------------
__global__ void k_out(const float* __restrict__ h, const float* __restrict__ W,
                      const float* __restrict__ b, float* __restrict__ out) {
    __shared__ float ws[256];
    int tid = threadIdx.x;
    if (tid < 256) ws[tid] = W[tid];
    __syncthreads();
    int warp = (blockIdx.x * blockDim.x + tid) >> 5;
    int lane = tid & 31;
    if (warp >= NODES) return;
    float4 v = *(const float4*)&h[(long)warp * 128 + lane * 4];
    int k = lane * 4;
    float s0 = v.x * ws[(k + 0) * 2] + v.y * ws[(k + 1) * 2] +
               v.z * ws[(k + 2) * 2] + v.w * ws[(k + 3) * 2];
    float s1 = v.x * ws[(k + 0) * 2 + 1] + v.y * ws[(k + 1) * 2 + 1] +
               v.z * ws[(k + 2) * 2 + 1] + v.w * ws[(k + 3) * 2 + 1];
#pragma unroll
    for (int o = 16; o; o >>= 1) {
        s0 += __shfl_xor_sync(0xFFFFFFFFu, s0, o);
        s1 += __shfl_xor_sync(0xFFFFFFFFu, s1, o);
    }
    if (lane == 0) {
        out[(long)warp * 2 + 0] = s0 + b[0];
        out[(long)warp * 2 + 1] = s1 + b[1];
    }
}

// ---------------- launch ----------------
extern "C" void kernel_launch(void* const* d_in, const int* in_sizes, int n_in,
                              void* d_out, int out_size) {
    int ix, iei, iwin, ibin, iwg, ibg, iwo1, ibo1, iwo2, ibo2;
    if (in_sizes[0] == 16384) {          // alphabetical (hedge)
        iwg = 0; iwin = 1; iwo1 = 2; iwo2 = 3;
        ibg = 4; ibin = 5; ibo1 = 6; ibo2 = 7;
        iei = 8; ix = 10;
    } else {                              // dict / insertion order
        ix = 0; iei = 1;
        iwin = 3; ibin = 4; iwg = 5; ibg = 6;
        iwo1 = 7; ibo1 = 8; iwo2 = 9; ibo2 = 10;
    }

    const float* x    = (const float*)d_in[ix];
    const int*   ei   = (const int*)d_in[iei];   // int32 (JAX x64 disabled)
    const float* W_in = (const float*)d_in[iwin];
    const float* b_in = (const float*)d_in[ibin];
    const float* W_g  = (const float*)d_in[iwg];
    const float* b_g  = (const float*)d_in[ibg];
    const float* W_o1 = (const float*)d_in[iwo1];
    const float* b_o1 = (const float*)d_in[ibo1];
    const float* W_o2 = (const float*)d_in[iwo2];
    const float* b_o2 = (const float*)d_in[ibo2];
    float* out = (float*)d_out;

    float *bufA, *bufB, *bufC;
    cudaGetSymbolAddress((void**)&bufA, g_bufA);
    cudaGetSymbolAddress((void**)&bufB, g_bufB);
    cudaGetSymbolAddress((void**)&bufC, g_bufC);
    __nv_bfloat16 *Bin_hi, *Bin_lo, *Bg_hi, *Bg_lo, *Bo1_hi, *Bo1_lo;
    cudaGetSymbolAddress((void**)&Bin_hi, g_Bin_hi);
    cudaGetSymbolAddress((void**)&Bin_lo, g_Bin_lo);
    cudaGetSymbolAddress((void**)&Bg_hi, g_Bg_hi);
    cudaGetSymbolAddress((void**)&Bg_lo, g_Bg_lo);
    cudaGetSymbolAddress((void**)&Bo1_hi, g_Bo1_hi);
    cudaGetSymbolAddress((void**)&Bo1_lo, g_Bo1_lo);

    int gemm_grid = (NODES + 127) / 128;          // 782
    int scat_grid = (EDGES * 32 + 255) / 256;

    // 0: zero deg + split/transpose weights
    k_prep<<<(NODES + 255) / 256, 256>>>(W_in, W_g, W_o1);
    // 1-2: degree + dinv
    k_deg<<<(EDGES + 255) / 256, 256>>>(ei);
    k_dinv<<<(NODES + 255) / 256, 256>>>();
    // 3 (profiled): h0 = leaky(x @ W_in + b_in) -> bufA   [K=239, KPAD=256]
    k_mma<true, false><<<gemm_grid, 256>>>(x, Bin_hi, Bin_lo, b_in, bufA, nullptr,
                                           NDIN, KPAD_IN);
    // 4: edge norms
    k_norm<<<(EDGES + 255) / 256, 256>>>(ei);

    // conv1: hw -> bufB ; agg(self+bias) -> bufC ; scatter into bufC
    k_mma<false, true><<<gemm_grid, 256>>>(bufA, Bg_hi, Bg_lo, b_g, bufB, bufC,
                                           DIM, DIM);
    k_scatter<<<scat_grid, 256>>>(ei, bufB, bufC);

    // conv2: hw -> bufB ; agg -> bufA ; scatter into bufA
    k_mma<false, true><<<gemm_grid, 256>>>(bufC, Bg_hi, Bg_lo, b_g, bufB, bufA,
                                           DIM, DIM);
    k_scatter<<<scat_grid, 256>>>(ei, bufB, bufA);

    // h3 = leaky(bufA @ W_o1 + b_o1) -> bufC
    k_mma<true, false><<<gemm_grid, 256>>>(bufA, Bo1_hi, Bo1_lo, b_o1, bufC, nullptr,
                                           DIM, DIM);

    // out = bufC @ W_o2 + b_o2
    k_out<<<(NODES * 32 + 255) / 256, 256>>>(bufC, W_o2, b_o2, out);
}

// round 12
// speedup vs baseline: 1.9324x; 1.0473x over previous
#include <cuda_runtime.h>
#include <cuda_bf16.h>
#include <cuda_fp16.h>
#include <cstdint>

#define NODES 100000
#define EDGES 640000
#define DIM   128
#define NDIN  239
#define KPAD_IN 256
#define NEG   0.01f
#define PITCH 40            // bf16 elems per smem row (80B, 16B-aligned, conflict-free)

// ---- scratch (__device__ globals; no allocs allowed) ----
__device__ float  g_bufA[(size_t)NODES * DIM];
__device__ float  g_bufB[(size_t)NODES * DIM];
__device__ float  g_bufC[(size_t)NODES * DIM];
__device__ __half g_hwH[(size_t)NODES * DIM];    // fp16 messages for scatter
__device__ float  g_deg[NODES];
__device__ float  g_dinv[NODES];
__device__ float  g_norm[EDGES];
// pre-transposed, bf16-split weights: B[n][k] = W[k][n]
__device__ __nv_bfloat16 g_Bin_hi[DIM * KPAD_IN];
__device__ __nv_bfloat16 g_Bin_lo[DIM * KPAD_IN];
__device__ __nv_bfloat16 g_Bg_hi[DIM * DIM];
__device__ __nv_bfloat16 g_Bg_lo[DIM * DIM];
__device__ __nv_bfloat16 g_Bo1_hi[DIM * DIM];
__device__ __nv_bfloat16 g_Bo1_lo[DIM * DIM];

// ---------------- helpers ----------------
__device__ __forceinline__ uint32_t smem_u32(const void* p) {
    uint32_t a;
    asm("{ .reg .u64 t; cvta.to.shared.u64 t, %1; cvt.u32.u64 %0, t; }" : "=r"(a) : "l"(p));
    return a;
}
__device__ __forceinline__ void ldsm4(uint32_t* r, uint32_t addr) {
    asm volatile("ldmatrix.sync.aligned.m8n8.x4.shared.b16 {%0,%1,%2,%3}, [%4];"
                 : "=r"(r[0]), "=r"(r[1]), "=r"(r[2]), "=r"(r[3]) : "r"(addr));
}
__device__ __forceinline__ void mma_bf16(float* c, const uint32_t* a,
                                         uint32_t b0, uint32_t b1) {
    asm volatile(
        "mma.sync.aligned.m16n8k16.row.col.f32.bf16.bf16.f32 "
        "{%0,%1,%2,%3}, {%4,%5,%6,%7}, {%8,%9}, {%0,%1,%2,%3};"
        : "+f"(c[0]), "+f"(c[1]), "+f"(c[2]), "+f"(c[3])
        : "r"(a[0]), "r"(a[1]), "r"(a[2]), "r"(a[3]), "r"(b0), "r"(b1));
}

// ---------------- graph structure + weight prep ----------------
__global__ void k_prep(const float* __restrict__ W_in, const float* __restrict__ W_g,
                       const float* __restrict__ W_o1) {
    int i = blockIdx.x * blockDim.x + threadIdx.x;
    if (i < NODES) g_deg[i] = 0.f;
    if (i < DIM * KPAD_IN) {              // W_in [239][128] -> Bin[n][256]
        int n = i / KPAD_IN, k = i % KPAD_IN;
        float v = (k < NDIN) ? W_in[k * DIM + n] : 0.f;
        __nv_bfloat16 h = __float2bfloat16(v);
        g_Bin_hi[i] = h;
        g_Bin_lo[i] = __float2bfloat16(v - __bfloat162float(h));
    }
    if (i < DIM * DIM) {                  // W_g, W_o1 [128][128] -> [n][128]
        int n = i / DIM, k = i % DIM;
        float v = W_g[k * DIM + n];
        __nv_bfloat16 h = __float2bfloat16(v);
        g_Bg_hi[i] = h;
        g_Bg_lo[i] = __float2bfloat16(v - __bfloat162float(h));
        float v2 = W_o1[k * DIM + n];
        __nv_bfloat16 h2 = __float2bfloat16(v2);
        g_Bo1_hi[i] = h2;
        g_Bo1_lo[i] = __float2bfloat16(v2 - __bfloat162float(h2));
    }
}

__global__ void k_deg(const int* __restrict__ ei) {
    int e = blockIdx.x * blockDim.x + threadIdx.x;
    if (e < EDGES) atomicAdd(&g_deg[ei[EDGES + e]], 1.f);
}
__global__ void k_dinv() {
    int i = blockIdx.x * blockDim.x + threadIdx.x;
    if (i < NODES) g_dinv[i] = rsqrtf(g_deg[i] + 1.f);
}
__global__ void k_norm(const int* __restrict__ ei) {
    int e = blockIdx.x * blockDim.x + threadIdx.x;
    if (e < EDGES) g_norm[e] = g_dinv[ei[e]] * g_dinv[ei[EDGES + e]];
}

// ================ HMMA GEMM: out = A[M,K] @ W[K,128] (+ fused epilogues) ================
// Block tile 128x128, 256 thr (8 warps: 4m x 2n), warp tile 32x64.
// bf16 hi/lo 3-term split (hh + lh + hl). 12 ldsm.x4 -> 48 MMAs per k16.
// MODE 0: outf = leaky(acc + bias)                       (fp32)
// MODE 1: outh = acc (fp16 hw); agg = acc*dinv^2 + bias  (fp32, self-loop fused)
// MODE 2: v = leaky(acc + bias); out2[r,0:2] = v . W2 + bo2
//         (partials combined across the two warp_n groups via smem)
template <int MODE>
__global__ void __launch_bounds__(256, 2)
k_mma(const float* __restrict__ A,
      const __nv_bfloat16* __restrict__ Bhi, const __nv_bfloat16* __restrict__ Blo,
      const float* __restrict__ bias,
      float* __restrict__ outf, __half* __restrict__ outh, float* __restrict__ agg,
      const float* __restrict__ W2, const float* __restrict__ bo2,
      float* __restrict__ out2,
      int K, int KPAD) {
    __shared__ __align__(16) __nv_bfloat16 sAh[128 * PITCH];
    __shared__ __align__(16) __nv_bfloat16 sAl[128 * PITCH];
    __shared__ __align__(16) __nv_bfloat16 sBh[128 * PITCH];
    __shared__ __align__(16) __nv_bfloat16 sBl[128 * PITCH];
    __shared__ float w2s[256];
    __shared__ float biass[128];

    int tid = threadIdx.x, wid = tid >> 5, lane = tid & 31;
    int warp_m = wid & 3, warp_n = wid >> 2;     // 4m x 2n
    int m0 = warp_m * 32, n0w = warp_n * 64;
    int row0 = blockIdx.x * 128;

    if (MODE == 2) {
        if (tid < 256) w2s[tid] = W2[tid];
        if (tid < 128) biass[tid] = bias[tid];
    }

    float acc[2][8][4];
#pragma unroll
    for (int mt = 0; mt < 2; mt++)
#pragma unroll
        for (int j = 0; j < 8; j++)
#pragma unroll
            for (int q = 0; q < 4; q++) acc[mt][j][q] = 0.f;

    uint32_t lrow = lane & 15;
    uint32_t kofB = (lane >> 4) * 16;            // bytes
    uint32_t adAh = smem_u32(sAh) + (m0 + lrow) * (PITCH * 2) + kofB;
    uint32_t adAl = smem_u32(sAl) + (m0 + lrow) * (PITCH * 2) + kofB;
    uint32_t adBh = smem_u32(sBh) + (n0w + lrow) * (PITCH * 2) + kofB;
    uint32_t adBl = smem_u32(sBl) + (n0w + lrow) * (PITCH * 2) + kofB;
    const uint32_t MT_OFF = 16 * (PITCH * 2);

    int nch = KPAD >> 5;                         // chunks of 32 k
    for (int ch = 0; ch < nch; ch++) {
        int k0 = ch << 5;
        // ---- stage A: 128 rows x 32 k fp32 -> hi/lo bf16 (16 rows per warp)
#pragma unroll
        for (int i = 0; i < 16; i++) {
            int r = wid + i * 8;
            int gr = row0 + r;
            if (gr >= NODES) gr = NODES - 1;     // clamp (results unused)
            int gc = k0 + lane;
            float v = (gc < K) ? A[(long)gr * K + gc] : 0.f;
            __nv_bfloat16 h = __float2bfloat16(v);
            sAh[r * PITCH + lane] = h;
            sAl[r * PITCH + lane] = __float2bfloat16(v - __bfloat162float(h));
        }
        // ---- stage B: 128 n-rows x 32 k bf16 hi/lo
#pragma unroll
        for (int p = 0; p < 8; p++) {
            int n = p * 16 + wid * 2 + (lane >> 4);
            int c2 = lane & 15;                  // b32 index (2 bf16)
            uint32_t vh = *(const uint32_t*)&Bhi[(long)n * KPAD + k0 + c2 * 2];
            uint32_t vl = *(const uint32_t*)&Blo[(long)n * KPAD + k0 + c2 * 2];
            *(uint32_t*)&sBh[n * PITCH + c2 * 2] = vh;
            *(uint32_t*)&sBl[n * PITCH + c2 * 2] = vl;
        }
        __syncthreads();

#pragma unroll
        for (int s = 0; s < 2; s++) {            // two k16 steps
            uint32_t kb = s * 32;
            uint32_t ah[2][4], al[2][4];
            ldsm4(ah[0], adAh + kb);
            ldsm4(al[0], adAl + kb);
            ldsm4(ah[1], adAh + MT_OFF + kb);
            ldsm4(al[1], adAl + MT_OFF + kb);
#pragma unroll
            for (int jp = 0; jp < 4; jp++) {
                uint32_t bh[4], bl[4];
                uint32_t jo = jp * 16 * (PITCH * 2);
                ldsm4(bh, adBh + jo + kb);
                ldsm4(bl, adBl + jo + kb);
#pragma unroll
                for (int mt = 0; mt < 2; mt++) {
#pragma unroll
                    for (int sub = 0; sub < 2; sub++) {
                        int j = jp * 2 + sub;
                        mma_bf16(acc[mt][j], ah[mt], bh[sub], bh[2 + sub]); // hi*hi
                        mma_bf16(acc[mt][j], al[mt], bh[sub], bh[2 + sub]); // lo*hi
                        mma_bf16(acc[mt][j], ah[mt], bl[sub], bl[2 + sub]); // hi*lo
                    }
                }
            }
        }
        __syncthreads();
    }

    int mr = lane >> 2;
    int c0 = (lane & 3) * 2;
    if (MODE == 2) {
        // fused leaky + projection. Partial dot per warp (its 64 cols); combine:
        // quad shfl (16 cols -> lane&3==0), then across warp_n via smem.
        float2 part[2][2];                        // [mt][h] partial (s0,s1)
#pragma unroll
        for (int mt = 0; mt < 2; mt++) {
#pragma unroll
            for (int h = 0; h < 2; h++) {
                float s0 = 0.f, s1 = 0.f;
#pragma unroll
                for (int j = 0; j < 8; j++) {
                    int n = n0w + j * 8 + c0;
                    float vx = acc[mt][j][h * 2]     + biass[n];
                    float vy = acc[mt][j][h * 2 + 1] + biass[n + 1];
                    vx = fmaxf(vx, NEG * vx);
                    vy = fmaxf(vy, NEG * vy);
                    s0 += vx * w2s[n * 2]     + vy * w2s[(n + 1) * 2];
                    s1 += vx * w2s[n * 2 + 1] + vy * w2s[(n + 1) * 2 + 1];
                }
                s0 += __shfl_xor_sync(0xFFFFFFFFu, s0, 1);
                s0 += __shfl_xor_sync(0xFFFFFFFFu, s0, 2);
                s1 += __shfl_xor_sync(0xFFFFFFFFu, s1, 1);
                s1 += __shfl_xor_sync(0xFFFFFFFFu, s1, 2);
                part[mt][h] = make_float2(s0, s1);
            }
        }
        float2* spart = (float2*)sAh;             // reuse A staging (mainloop done)
        __syncthreads();
        if (warp_n == 1 && (lane & 3) == 0) {
#pragma unroll
            for (int mt = 0; mt < 2; mt++)
#pragma unroll
                for (int h = 0; h < 2; h++)
                    spart[m0 + mt * 16 + mr + h * 8] = part[mt][h];
        }
        __syncthreads();
        if (warp_n == 0 && (lane & 3) == 0) {
#pragma unroll
            for (int mt = 0; mt < 2; mt++) {
#pragma unroll
                for (int h = 0; h < 2; h++) {
                    int lr = m0 + mt * 16 + mr + h * 8;
                    int r = row0 + lr;
                    if (r >= NODES) continue;
                    float2 o = spart[lr];
                    out2[(long)r * 2 + 0] = part[mt][h].x + o.x + bo2[0];
                    out2[(long)r * 2 + 1] = part[mt][h].y + o.y + bo2[1];
                }
            }
        }
        return;
    }
#pragma unroll
    for (int mt = 0; mt < 2; mt++) {
#pragma unroll
        for (int j = 0; j < 8; j++) {
            int n = n0w + j * 8 + c0;
            float2 b2 = *(const float2*)&bias[n];
#pragma unroll
            for (int h = 0; h < 2; h++) {
                int r = row0 + m0 + mt * 16 + mr + h * 8;
                if (r >= NODES) continue;
                float vx = acc[mt][j][h * 2], vy = acc[mt][j][h * 2 + 1];
                long base = (long)r * DIM + n;
                if (MODE == 1) {
                    *(__half2*)&outh[base] = __floats2half2_rn(vx, vy); // fp16 hw
                    float d = g_dinv[r];
                    float s = d * d;
                    *(float2*)&agg[base] =
                        make_float2(fmaf(vx, s, b2.x), fmaf(vy, s, b2.y));
                } else {
                    vx += b2.x; vy += b2.y;
                    vx = fmaxf(vx, NEG * vx);
                    vy = fmaxf(vy, NEG * vy);
                    *(float2*)&outf[base] = make_float2(vx, vy);
                }
            }
        }
    }
}

// ---------------- edge scatter: agg[dst] += hw[src]*norm (hw in fp16) ----------------
__global__ void k_scatter(const int* __restrict__ ei,
                          const __half* __restrict__ hw,
                          float* __restrict__ agg) {
    int idx = blockIdx.x * blockDim.x + threadIdx.x;
    int e = idx >> 5;
    int c = idx & 31;
    if (e >= EDGES) return;
    int src = ei[e];
    int dst = ei[EDGES + e];
    float n = g_norm[e];
    uint2 u = *(const uint2*)&hw[(long)src * 128 + c * 4];
    float2 p0 = __half22float2(*(__half2*)&u.x);
    float2 p1 = __half22float2(*(__half2*)&u.y);
    float* p = &agg[(long)dst * 128 + c * 4];
    asm volatile("red.global.add.v4.f32 [%0], {%1, %2, %3, %4};"
                 :: "l"(p), "f"(p0.x * n), "f"(p0.y * n), "f"(p1.x * n), "f"(p1.y * n)
                 : "memory");
}

// ---------------- launch ----------------
extern "C" void kernel_launch(void* const* d_in, const int* in_sizes, int n_in,
                              void* d_out, int out_size) {
    int ix, iei, iwin, ibin, iwg, ibg, iwo1, ibo1, iwo2, ibo2;
    if (in_sizes[0] == 16384) {          // alphabetical (hedge)
        iwg = 0; iwin = 1; iwo1 = 2; iwo2 = 3;
        ibg = 4; ibin = 5; ibo1 = 6; ibo2 = 7;
        iei = 8; ix = 10;
    } else {                              // dict / insertion order
        ix = 0; iei = 1;
        iwin = 3; ibin = 4; iwg = 5; ibg = 6;
        iwo1 = 7; ibo1 = 8; iwo2 = 9; ibo2 = 10;
    }

    const float* x    = (const float*)d_in[ix];
    const int*   ei   = (const int*)d_in[iei];   // int32 (JAX x64 disabled)
    const float* W_in = (const float*)d_in[iwin];
    const float* b_in = (const float*)d_in[ibin];
    const float* W_g  = (const float*)d_in[iwg];
    const float* b_g  = (const float*)d_in[ibg];
    const float* W_o1 = (const float*)d_in[iwo1];
    const float* b_o1 = (const float*)d_in[ibo1];
    const float* W_o2 = (const float*)d_in[iwo2];
    const float* b_o2 = (const float*)d_in[ibo2];
    float* out = (float*)d_out;

    float *bufA, *bufB, *bufC;
    __half* hwH;
    cudaGetSymbolAddress((void**)&bufA, g_bufA);
    cudaGetSymbolAddress((void**)&bufB, g_bufB);
    cudaGetSymbolAddress((void**)&bufC, g_bufC);
    cudaGetSymbolAddress((void**)&hwH, g_hwH);
    __nv_bfloat16 *Bin_hi, *Bin_lo, *Bg_hi, *Bg_lo, *Bo1_hi, *Bo1_lo;
    cudaGetSymbolAddress((void**)&Bin_hi, g_Bin_hi);
    cudaGetSymbolAddress((void**)&Bin_lo, g_Bin_lo);
    cudaGetSymbolAddress((void**)&Bg_hi, g_Bg_hi);
    cudaGetSymbolAddress((void**)&Bg_lo, g_Bg_lo);
    cudaGetSymbolAddress((void**)&Bo1_hi, g_Bo1_hi);
    cudaGetSymbolAddress((void**)&Bo1_lo, g_Bo1_lo);

    int gemm_grid = (NODES + 127) / 128;          // 782
    int scat_grid = (EDGES * 32 + 255) / 256;

    // 0: zero deg + split/transpose weights
    k_prep<<<(NODES + 255) / 256, 256>>>(W_in, W_g, W_o1);
    // 1-2: degree + dinv
    k_deg<<<(EDGES + 255) / 256, 256>>>(ei);
    k_dinv<<<(NODES + 255) / 256, 256>>>();
    // 3 (profiled): h0 = leaky(x @ W_in + b_in) -> bufA   [K=239, KPAD=256]
    k_mma<0><<<gemm_grid, 256>>>(x, Bin_hi, Bin_lo, b_in, bufA, nullptr, nullptr,
                                 nullptr, nullptr, nullptr, NDIN, KPAD_IN);
    // 4: edge norms
    k_norm<<<(EDGES + 255) / 256, 256>>>(ei);

    // conv1: hw -> hwH (fp16) ; agg(self+bias) -> bufC ; scatter into bufC
    k_mma<1><<<gemm_grid, 256>>>(bufA, Bg_hi, Bg_lo, b_g, nullptr, hwH, bufC,
                                 nullptr, nullptr, nullptr, DIM, DIM);
    k_scatter<<<scat_grid, 256>>>(ei, hwH, bufC);

    // conv2: hw -> hwH ; agg -> bufB ; scatter into bufB
    k_mma<1><<<gemm_grid, 256>>>(bufC, Bg_hi, Bg_lo, b_g, nullptr, hwH, bufB,
                                 nullptr, nullptr, nullptr, DIM, DIM);
    k_scatter<<<scat_grid, 256>>>(ei, hwH, bufB);

    // final: leaky(bufB @ W_o1 + b_o1) @ W_o2 + b_o2 -> out (fully fused)
    k_mma<2><<<gemm_grid, 256>>>(bufB, Bo1_hi, Bo1_lo, b_o1, nullptr, nullptr, nullptr,
                                 W_o2, b_o2, out, DIM, DIM);
}

// round 13
// speedup vs baseline: 2.0106x; 1.0405x over previous
#include <cuda_runtime.h>
#include <cuda_bf16.h>
#include <cuda_fp16.h>
#include <cstdint>

#define NODES 100000
#define EDGES 640000
#define DIM   128
#define NDIN  239
#define KPAD_IN 256
#define NEG   0.01f
#define PITCH 72            // bf16 elems per smem row (144B = 9*16B, conflict-free ldsm)

// smem plane offsets (dynamic)
#define OFF_AH 0
#define OFF_AL 18432
#define OFF_BH 36864
#define OFF_BL 55296
#define OFF_W2 73728        // 256 floats
#define OFF_BI 74752        // 128 floats
#define SMEM_SZ 75264

// ---- scratch (__device__ globals; no allocs allowed) ----
__device__ float  g_bufA[(size_t)NODES * DIM];
__device__ float  g_bufB[(size_t)NODES * DIM];
__device__ float  g_bufC[(size_t)NODES * DIM];
__device__ __half g_hwH[(size_t)NODES * DIM];    // fp16 messages for scatter
__device__ float  g_deg[NODES];
__device__ float  g_dinv[NODES];
// pre-transposed, bf16-split weights: B[n][k] = W[k][n]
__device__ __nv_bfloat16 g_Bin_hi[DIM * KPAD_IN];
__device__ __nv_bfloat16 g_Bin_lo[DIM * KPAD_IN];
__device__ __nv_bfloat16 g_Bg_hi[DIM * DIM];
__device__ __nv_bfloat16 g_Bg_lo[DIM * DIM];
__device__ __nv_bfloat16 g_Bo1_hi[DIM * DIM];
__device__ __nv_bfloat16 g_Bo1_lo[DIM * DIM];

// ---------------- helpers ----------------
__device__ __forceinline__ uint32_t smem_u32(const void* p) {
    uint32_t a;
    asm("{ .reg .u64 t; cvta.to.shared.u64 t, %1; cvt.u32.u64 %0, t; }" : "=r"(a) : "l"(p));
    return a;
}
__device__ __forceinline__ void ldsm4(uint32_t* r, uint32_t addr) {
    asm volatile("ldmatrix.sync.aligned.m8n8.x4.shared.b16 {%0,%1,%2,%3}, [%4];"
                 : "=r"(r[0]), "=r"(r[1]), "=r"(r[2]), "=r"(r[3]) : "r"(addr));
}
__device__ __forceinline__ void mma_bf16(float* c, const uint32_t* a,
                                         uint32_t b0, uint32_t b1) {
    asm volatile(
        "mma.sync.aligned.m16n8k16.row.col.f32.bf16.bf16.f32 "
        "{%0,%1,%2,%3}, {%4,%5,%6,%7}, {%8,%9}, {%0,%1,%2,%3};"
        : "+f"(c[0]), "+f"(c[1]), "+f"(c[2]), "+f"(c[3])
        : "r"(a[0]), "r"(a[1]), "r"(a[2]), "r"(a[3]), "r"(b0), "r"(b1));
}
__device__ __forceinline__ void cp16(uint32_t dst, const void* src) {
    asm volatile("cp.async.cg.shared.global [%0], [%1], 16;" :: "r"(dst), "l"(src));
}

// ---------------- graph structure + weight prep ----------------
__global__ void k_prep(const float* __restrict__ W_in, const float* __restrict__ W_g,
                       const float* __restrict__ W_o1) {
    int i = blockIdx.x * blockDim.x + threadIdx.x;
    if (i < NODES) g_deg[i] = 0.f;
    if (i < DIM * KPAD_IN) {              // W_in [239][128] -> Bin[n][256]
        int n = i / KPAD_IN, k = i % KPAD_IN;
        float v = (k < NDIN) ? W_in[k * DIM + n] : 0.f;
        __nv_bfloat16 h = __float2bfloat16(v);
        g_Bin_hi[i] = h;
        g_Bin_lo[i] = __float2bfloat16(v - __bfloat162float(h));
    }
    if (i < DIM * DIM) {                  // W_g, W_o1 [128][128] -> [n][128]
        int n = i / DIM, k = i % DIM;
        float v = W_g[k * DIM + n];
        __nv_bfloat16 h = __float2bfloat16(v);
        g_Bg_hi[i] = h;
        g_Bg_lo[i] = __float2bfloat16(v - __bfloat162float(h));
        float v2 = W_o1[k * DIM + n];
        __nv_bfloat16 h2 = __float2bfloat16(v2);
        g_Bo1_hi[i] = h2;
        g_Bo1_lo[i] = __float2bfloat16(v2 - __bfloat162float(h2));
    }
}

__global__ void k_deg(const int* __restrict__ ei) {
    int e = blockIdx.x * blockDim.x + threadIdx.x;
    if (e < EDGES) atomicAdd(&g_deg[ei[EDGES + e]], 1.f);
}
__global__ void k_dinv() {
    int i = blockIdx.x * blockDim.x + threadIdx.x;
    if (i < NODES) g_dinv[i] = rsqrtf(g_deg[i] + 1.f);
}

// ================ HMMA GEMM: out = A[M,K] @ W[K,128] (+ fused epilogues) ================
// Block tile 128x128, 256 thr (8 warps: 4m x 2n), warp tile 32x64.
// KC=64 chunks; B staged via cp.async (pre-split bf16); A converted fp32->hi/lo bf16x2.
// bf16 hi/lo 3-term split (hh + lh + hl).
// MODE 0: outf = leaky(acc + bias)
// MODE 1: outh = acc (fp16 hw); agg = acc*dinv^2 + bias  (self-loop fused)
// MODE 2: v = leaky(acc + bias); out2[r,0:2] = v . W2 + bo2 (cross-warp_n via smem)
template <int MODE>
__global__ void __launch_bounds__(256, 2)
k_mma(const float* __restrict__ A,
      const __nv_bfloat16* __restrict__ Bhi, const __nv_bfloat16* __restrict__ Blo,
      const float* __restrict__ bias,
      float* __restrict__ outf, __half* __restrict__ outh, float* __restrict__ agg,
      const float* __restrict__ W2, const float* __restrict__ bo2,
      float* __restrict__ out2,
      int K, int KPAD) {
    extern __shared__ __align__(16) char smem[];
    __nv_bfloat16* sAh = (__nv_bfloat16*)(smem + OFF_AH);
    __nv_bfloat16* sAl = (__nv_bfloat16*)(smem + OFF_AL);
    float* w2s  = (float*)(smem + OFF_W2);
    float* biass = (float*)(smem + OFF_BI);
    uint32_t sb = smem_u32(smem);

    int tid = threadIdx.x, wid = tid >> 5, lane = tid & 31;
    int warp_m = wid & 3, warp_n = wid >> 2;     // 4m x 2n
    int m0 = warp_m * 32, n0w = warp_n * 64;
    int row0 = blockIdx.x * 128;

    if (MODE == 2) {
        if (tid < 256) w2s[tid] = W2[tid];
        if (tid < 128) biass[tid] = bias[tid];
    }

    float acc[2][8][4];
#pragma unroll
    for (int mt = 0; mt < 2; mt++)
#pragma unroll
        for (int j = 0; j < 8; j++)
#pragma unroll
            for (int q = 0; q < 4; q++) acc[mt][j][q] = 0.f;

    uint32_t lrow = lane & 15;
    uint32_t kofB = (lane >> 4) * 16;            // bytes
    uint32_t adAh = sb + OFF_AH + (m0 + lrow) * 144 + kofB;
    uint32_t adAl = sb + OFF_AL + (m0 + lrow) * 144 + kofB;
    uint32_t adBh = sb + OFF_BH + (n0w + lrow) * 144 + kofB;
    uint32_t adBl = sb + OFF_BL + (n0w + lrow) * 144 + kofB;
    const uint32_t MT_OFF = 16 * 144;

    // B cp.async addressing: thread t -> row n = t>>1, 64B half = t&1
    int bn = tid >> 1, bhalf = tid & 1;
    uint32_t bdst_h = sb + OFF_BH + bn * 144 + bhalf * 64;
    uint32_t bdst_l = sb + OFF_BL + bn * 144 + bhalf * 64;

    bool oddK = (K & 1);
    int nch = KPAD >> 6;                         // chunks of 64 k
    for (int ch = 0; ch < nch; ch++) {
        int k0 = ch << 6;
        // ---- B: pure 16B async copies (bf16 pre-split)
        {
            const char* sh = (const char*)&Bhi[(long)bn * KPAD + k0] + bhalf * 64;
            const char* sl = (const char*)&Blo[(long)bn * KPAD + k0] + bhalf * 64;
#pragma unroll
            for (int j = 0; j < 4; j++) {
                cp16(bdst_h + j * 16, sh + j * 16);
                cp16(bdst_l + j * 16, sl + j * 16);
            }
            asm volatile("cp.async.commit_group;" ::: "memory");
        }
        // ---- A: 128 rows x 64 k fp32 -> hi/lo bf16x2 (16 rows/warp, 2 cols/lane)
#pragma unroll
        for (int i = 0; i < 16; i++) {
            int r = wid + i * 8;
            int gr = row0 + r;
            if (gr >= NODES) gr = NODES - 1;     // clamp (rows unused in epilogue)
            int gc = k0 + 2 * lane;
            const float* ap = &A[(long)gr * K + gc];
            float v0 = 0.f, v1 = 0.f;
            if (!oddK) {
                float2 t = *(const float2*)ap;   // K even: 8B aligned
                v0 = t.x; v1 = t.y;
            } else {
                if (gc < K)     v0 = ap[0];
                if (gc + 1 < K) v1 = ap[1];
            }
            __nv_bfloat16 h0 = __float2bfloat16(v0);
            __nv_bfloat16 h1 = __float2bfloat16(v1);
            __nv_bfloat16 l0 = __float2bfloat16(v0 - __bfloat162float(h0));
            __nv_bfloat16 l1 = __float2bfloat16(v1 - __bfloat162float(h1));
            ((__nv_bfloat162*)(sAh + r * PITCH))[lane] = __halves2bfloat162(h0, h1);
            ((__nv_bfloat162*)(sAl + r * PITCH))[lane] = __halves2bfloat162(l0, l1);
        }
        asm volatile("cp.async.wait_group 0;" ::: "memory");
        __syncthreads();

#pragma unroll
        for (int s = 0; s < 4; s++) {            // four k16 steps
            uint32_t kb = s * 32;
            uint32_t ah[2][4], al[2][4];
            ldsm4(ah[0], adAh + kb);
            ldsm4(al[0], adAl + kb);
            ldsm4(ah[1], adAh + MT_OFF + kb);
            ldsm4(al[1], adAl + MT_OFF + kb);
#pragma unroll
            for (int jp = 0; jp < 4; jp++) {
                uint32_t bh[4], bl[4];
                uint32_t jo = jp * 16 * 144;
                ldsm4(bh, adBh + jo + kb);
                ldsm4(bl, adBl + jo + kb);
#pragma unroll
                for (int mt = 0; mt < 2; mt++) {
#pragma unroll
                    for (int sub = 0; sub < 2; sub++) {
                        int j = jp * 2 + sub;
                        mma_bf16(acc[mt][j], ah[mt], bh[sub], bh[2 + sub]); // hi*hi
                        mma_bf16(acc[mt][j], al[mt], bh[sub], bh[2 + sub]); // lo*hi
                        mma_bf16(acc[mt][j], ah[mt], bl[sub], bl[2 + sub]); // hi*lo
                    }
                }
            }
        }
        __syncthreads();
    }

    int mr = lane >> 2;
    int c0 = (lane & 3) * 2;
    if (MODE == 2) {
        float2 part[2][2];
#pragma unroll
        for (int mt = 0; mt < 2; mt++) {
#pragma unroll
            for (int h = 0; h < 2; h++) {
                float s0 = 0.f, s1 = 0.f;
#pragma unroll
                for (int j = 0; j < 8; j++) {
                    int n = n0w + j * 8 + c0;
                    float vx = acc[mt][j][h * 2]     + biass[n];
                    float vy = acc[mt][j][h * 2 + 1] + biass[n + 1];
                    vx = fmaxf(vx, NEG * vx);
                    vy = fmaxf(vy, NEG * vy);
                    s0 += vx * w2s[n * 2]     + vy * w2s[(n + 1) * 2];
                    s1 += vx * w2s[n * 2 + 1] + vy * w2s[(n + 1) * 2 + 1];
                }
                s0 += __shfl_xor_sync(0xFFFFFFFFu, s0, 1);
                s0 += __shfl_xor_sync(0xFFFFFFFFu, s0, 2);
                s1 += __shfl_xor_sync(0xFFFFFFFFu, s1, 1);
                s1 += __shfl_xor_sync(0xFFFFFFFFu, s1, 2);
                part[mt][h] = make_float2(s0, s1);
            }
        }
        float2* spart = (float2*)sAh;             // reuse A staging
        __syncthreads();
        if (warp_n == 1 && (lane & 3) == 0) {
#pragma unroll
            for (int mt = 0; mt < 2; mt++)
#pragma unroll
                for (int h = 0; h < 2; h++)
                    spart[m0 + mt * 16 + mr + h * 8] = part[mt][h];
        }
        __syncthreads();
        if (warp_n == 0 && (lane & 3) == 0) {
#pragma unroll
            for (int mt = 0; mt < 2; mt++) {
#pragma unroll
                for (int h = 0; h < 2; h++) {
                    int lr = m0 + mt * 16 + mr + h * 8;
                    int r = row0 + lr;
                    if (r >= NODES) continue;
                    float2 o = spart[lr];
                    out2[(long)r * 2 + 0] = part[mt][h].x + o.x + bo2[0];
                    out2[(long)r * 2 + 1] = part[mt][h].y + o.y + bo2[1];
                }
            }
        }
        return;
    }
#pragma unroll
    for (int mt = 0; mt < 2; mt++) {
#pragma unroll
        for (int j = 0; j < 8; j++) {
            int n = n0w + j * 8 + c0;
            float2 b2 = *(const float2*)&bias[n];
#pragma unroll
            for (int h = 0; h < 2; h++) {
                int r = row0 + m0 + mt * 16 + mr + h * 8;
                if (r >= NODES) continue;
                float vx = acc[mt][j][h * 2], vy = acc[mt][j][h * 2 + 1];
                long base = (long)r * DIM + n;
                if (MODE == 1) {
                    *(__half2*)&outh[base] = __floats2half2_rn(vx, vy); // fp16 hw
                    float d = g_dinv[r];
                    float s = d * d;
                    *(float2*)&agg[base] =
                        make_float2(fmaf(vx, s, b2.x), fmaf(vy, s, b2.y));
                } else {
                    vx += b2.x; vy += b2.y;
                    vx = fmaxf(vx, NEG * vx);
                    vy = fmaxf(vy, NEG * vy);
                    *(float2*)&outf[base] = make_float2(vx, vy);
                }
            }
        }
    }
}

// ---------------- edge scatter: agg[dst] += hw[src]*dinv[s]*dinv[d] (fp16 msgs) -------
__global__ void k_scatter(const int* __restrict__ ei,
                          const __half* __restrict__ hw,
                          float* __restrict__ agg) {
    int idx = blockIdx.x * blockDim.x + threadIdx.x;
    int e = idx >> 5;
    int c = idx & 31;
    if (e >= EDGES) return;
    int src = ei[e];
    int dst = ei[EDGES + e];
    float n = g_dinv[src] * g_dinv[dst];        // broadcast loads (L1-hot)
    uint2 u = *(const uint2*)&hw[(long)src * 128 + c * 4];
    float2 p0 = __half22float2(*(__half2*)&u.x);
    float2 p1 = __half22float2(*(__half2*)&u.y);
    float* p = &agg[(long)dst * 128 + c * 4];
    asm volatile("red.global.add.v4.f32 [%0], {%1, %2, %3, %4};"
                 :: "l"(p), "f"(p0.x * n), "f"(p0.y * n), "f"(p1.x * n), "f"(p1.y * n)
                 : "memory");
}

// ---------------- launch ----------------
extern "C" void kernel_launch(void* const* d_in, const int* in_sizes, int n_in,
                              void* d_out, int out_size) {
    int ix, iei, iwin, ibin, iwg, ibg, iwo1, ibo1, iwo2, ibo2;
    if (in_sizes[0] == 16384) {          // alphabetical (hedge)
        iwg = 0; iwin = 1; iwo1 = 2; iwo2 = 3;
        ibg = 4; ibin = 5; ibo1 = 6; ibo2 = 7;
        iei = 8; ix = 10;
    } else {                              // dict / insertion order
        ix = 0; iei = 1;
        iwin = 3; ibin = 4; iwg = 5; ibg = 6;
        iwo1 = 7; ibo1 = 8; iwo2 = 9; ibo2 = 10;
    }

    const float* x    = (const float*)d_in[ix];
    const int*   ei   = (const int*)d_in[iei];   // int32 (JAX x64 disabled)
    const float* W_in = (const float*)d_in[iwin];
    const float* b_in = (const float*)d_in[ibin];
    const float* W_g  = (const float*)d_in[iwg];
    const float* b_g  = (const float*)d_in[ibg];
    const float* W_o1 = (const float*)d_in[iwo1];
    const float* b_o1 = (const float*)d_in[ibo1];
    const float* W_o2 = (const float*)d_in[iwo2];
    const float* b_o2 = (const float*)d_in[ibo2];
    float* out = (float*)d_out;

    float *bufA, *bufB, *bufC;
    __half* hwH;
    cudaGetSymbolAddress((void**)&bufA, g_bufA);
    cudaGetSymbolAddress((void**)&bufB, g_bufB);
    cudaGetSymbolAddress((void**)&bufC, g_bufC);
    cudaGetSymbolAddress((void**)&hwH, g_hwH);
    __nv_bfloat16 *Bin_hi, *Bin_lo, *Bg_hi, *Bg_lo, *Bo1_hi, *Bo1_lo;
    cudaGetSymbolAddress((void**)&Bin_hi, g_Bin_hi);
    cudaGetSymbolAddress((void**)&Bin_lo, g_Bin_lo);
    cudaGetSymbolAddress((void**)&Bg_hi, g_Bg_hi);
    cudaGetSymbolAddress((void**)&Bg_lo, g_Bg_lo);
    cudaGetSymbolAddress((void**)&Bo1_hi, g_Bo1_hi);
    cudaGetSymbolAddress((void**)&Bo1_lo, g_Bo1_lo);

    static bool attr_set = false;
    if (!attr_set) {
        cudaFuncSetAttribute(k_mma<0>, cudaFuncAttributeMaxDynamicSharedMemorySize, SMEM_SZ);
        cudaFuncSetAttribute(k_mma<1>, cudaFuncAttributeMaxDynamicSharedMemorySize, SMEM_SZ);
        cudaFuncSetAttribute(k_mma<2>, cudaFuncAttributeMaxDynamicSharedMemorySize, SMEM_SZ);
        attr_set = true;
    }

    int gemm_grid = (NODES + 127) / 128;          // 782
    int scat_grid = (EDGES * 32 + 255) / 256;

    // 0: zero deg + split/transpose weights
    k_prep<<<(NODES + 255) / 256, 256>>>(W_in, W_g, W_o1);
    // 1-2: degree + dinv
    k_deg<<<(EDGES + 255) / 256, 256>>>(ei);
    k_dinv<<<(NODES + 255) / 256, 256>>>();
    // 3 (profiled): h0 = leaky(x @ W_in + b_in) -> bufA   [K=239, KPAD=256]
    k_mma<0><<<gemm_grid, 256, SMEM_SZ>>>(x, Bin_hi, Bin_lo, b_in, bufA, nullptr,
                                          nullptr, nullptr, nullptr, nullptr,
                                          NDIN, KPAD_IN);

    // conv1: hw -> hwH (fp16) ; agg(self+bias) -> bufC ; scatter into bufC
    k_mma<1><<<gemm_grid, 256, SMEM_SZ>>>(bufA, Bg_hi, Bg_lo, b_g, nullptr, hwH, bufC,
                                          nullptr, nullptr, nullptr, DIM, DIM);
    k_scatter<<<scat_grid, 256>>>(ei, hwH, bufC);

    // conv2: hw -> hwH ; agg -> bufB ; scatter into bufB
    k_mma<1><<<gemm_grid, 256, SMEM_SZ>>>(bufC, Bg_hi, Bg_lo, b_g, nullptr, hwH, bufB,
                                          nullptr, nullptr, nullptr, DIM, DIM);
    k_scatter<<<scat_grid, 256>>>(ei, hwH, bufB);

    // final: leaky(bufB @ W_o1 + b_o1) @ W_o2 + b_o2 -> out (fully fused)
    k_mma<2><<<gemm_grid, 256, SMEM_SZ>>>(bufB, Bo1_hi, Bo1_lo, b_o1, nullptr, nullptr,
                                          nullptr, W_o2, b_o2, out, DIM, DIM);
}